// round 7
// baseline (speedup 1.0000x reference)
#include <cuda_runtime.h>
#include <cuda_bf16.h>
#include <math.h>
#include <stdint.h>

// Problem constants (fixed for this dataset)
#define N_NODES 4096
#define FEAT    128
#define HID     256
#define KCL     1024
#define NE      131072

// ==================== device scratch ====================
__device__ __align__(16) int   d_cnt_in [N_NODES];
__device__ __align__(16) int   d_cnt_out[N_NODES];
__device__ __align__(16) int   d_selfc  [N_NODES];
__device__ __align__(16) int   d_cur_in [N_NODES];
__device__ __align__(16) int   d_cur_out[N_NODES];
__device__ __align__(16) int   d_off_in [N_NODES];
__device__ __align__(16) int   d_off_out[N_NODES];
__device__ __align__(16) int   d_csc_src[NE];
__device__ __align__(16) int   d_csr_dst[NE];
__device__ __align__(16) float d_dis_sp [N_NODES];
__device__ __align__(16) float d_dis_dn [N_NODES];
__device__ double d_scal[4];   // [0]=ent [1]=cross [2]=sum adj^2 [3]=||G||^2

__device__ __align__(16) float g_x1 [N_NODES*HID];
__device__ __align__(16) float g_x2 [N_NODES*HID];
__device__ __align__(16) float g_xw [N_NODES*KCL];
__device__ __align__(16) float g_s  [N_NODES*KCL];
__device__ __align__(16) float g_t  [N_NODES*KCL];
__device__ __align__(16) float g_M  [N_NODES*KCL];
__device__ __align__(16) float g_xp [KCL*HID];
__device__ __align__(16) float g_adjp[KCL*KCL];
__device__ __align__(16) float g_G  [KCL*KCL];
__device__ __align__(16) float g_xo [N_NODES*HID];

// bf16 split operand buffers
__device__ __align__(16) __nv_bfloat16 g_nhi [N_NODES*FEAT],  g_nlo [N_NODES*FEAT];
__device__ __align__(16) __nv_bfloat16 g_xhi [N_NODES*HID],   g_xlo [N_NODES*HID];
__device__ __align__(16) __nv_bfloat16 g_wthi[KCL*HID],       g_wtlo[KCL*HID];
__device__ __align__(16) __nv_bfloat16 g_shi [N_NODES*KCL],   g_slo [N_NODES*KCL];
__device__ __align__(16) __nv_bfloat16 g_sthi[KCL*N_NODES],   g_stlo[KCL*N_NODES];
__device__ __align__(16) __nv_bfloat16 g_x2thi[HID*N_NODES],  g_x2tlo[HID*N_NODES];
__device__ __align__(16) __nv_bfloat16 g_tthi[KCL*N_NODES],   g_ttlo[KCL*N_NODES];
__device__ __align__(16) __nv_bfloat16 g_xpthi[HID*KCL],      g_xptlo[HID*KCL];
__device__ __align__(16) __nv_bfloat16 g_apthi[KCL*KCL],      g_aptlo[KCL*KCL];
__device__ __align__(16) __nv_bfloat16 g_mbhi[N_NODES*KCL],   g_mblo[N_NODES*KCL];

// ==================== setup kernels ====================
__global__ void init_zero_kernel() {
    int i = blockIdx.x * blockDim.x + threadIdx.x;
    if (i < N_NODES) {
        d_cnt_in[i] = 0; d_cnt_out[i] = 0; d_selfc[i] = 0;
        d_cur_in[i] = 0; d_cur_out[i] = 0;
    }
    if (i < 4) d_scal[i] = 0.0;
}

__global__ void zero_kernel(float* __restrict__ p, int n) {
    int i = (blockIdx.x * blockDim.x + threadIdx.x) * 4;
    if (i < n) *reinterpret_cast<float4*>(p + i) = make_float4(0.f, 0.f, 0.f, 0.f);
}

__global__ void count_kernel(const int* __restrict__ ei, int E) {
    int e = blockIdx.x * blockDim.x + threadIdx.x;
    if (e >= E) return;
    int r = ei[e];
    int c = ei[E + e];
    atomicAdd(&d_cnt_out[r], 1);
    atomicAdd(&d_cnt_in[c], 1);
    if (r == c) atomicAdd(&d_selfc[r], 1);
}

__global__ void scan_kernel() {
    __shared__ int sh[1024];
    int t = threadIdx.x;
    {
        int v = t * 4;
        int a0 = d_cnt_in[v], a1 = d_cnt_in[v+1], a2 = d_cnt_in[v+2], a3 = d_cnt_in[v+3];
        int tot = a0 + a1 + a2 + a3;
        sh[t] = tot; __syncthreads();
        for (int o = 1; o < 1024; o <<= 1) {
            int x = (t >= o) ? sh[t - o] : 0;
            __syncthreads();
            sh[t] += x;
            __syncthreads();
        }
        int excl = sh[t] - tot;
        d_off_in[v]   = excl;
        d_off_in[v+1] = excl + a0;
        d_off_in[v+2] = excl + a0 + a1;
        d_off_in[v+3] = excl + a0 + a1 + a2;
        d_dis_sp[v]   = rsqrtf((float)(a0 + 1));
        d_dis_sp[v+1] = rsqrtf((float)(a1 + 1));
        d_dis_sp[v+2] = rsqrtf((float)(a2 + 1));
        d_dis_sp[v+3] = rsqrtf((float)(a3 + 1));
        __syncthreads();
    }
    {
        int v = t * 4;
        int a0 = d_cnt_out[v], a1 = d_cnt_out[v+1], a2 = d_cnt_out[v+2], a3 = d_cnt_out[v+3];
        int tot = a0 + a1 + a2 + a3;
        sh[t] = tot; __syncthreads();
        for (int o = 1; o < 1024; o <<= 1) {
            int x = (t >= o) ? sh[t - o] : 0;
            __syncthreads();
            sh[t] += x;
            __syncthreads();
        }
        int excl = sh[t] - tot;
        d_off_out[v]   = excl;
        d_off_out[v+1] = excl + a0;
        d_off_out[v+2] = excl + a0 + a1;
        d_off_out[v+3] = excl + a0 + a1 + a2;
        d_dis_dn[v]   = rsqrtf((float)(a0 - d_selfc[v]   + 1));
        d_dis_dn[v+1] = rsqrtf((float)(a1 - d_selfc[v+1] + 1));
        d_dis_dn[v+2] = rsqrtf((float)(a2 - d_selfc[v+2] + 1));
        d_dis_dn[v+3] = rsqrtf((float)(a3 - d_selfc[v+3] + 1));
    }
}

__global__ void fill_kernel(const int* __restrict__ ei, int E) {
    int e = blockIdx.x * blockDim.x + threadIdx.x;
    if (e >= E) return;
    int r = ei[e];
    int c = ei[E + e];
    int p = atomicAdd(&d_cur_in[c], 1);
    d_csc_src[d_off_in[c] + p] = r;
    int q = atomicAdd(&d_cur_out[r], 1);
    d_csr_dst[d_off_out[r] + q] = c;
}

// ==================== split / transpose-split ====================
__global__ void split_kernel(const float* __restrict__ in,
                             __nv_bfloat16* __restrict__ hi,
                             __nv_bfloat16* __restrict__ lo, int n)
{
    int i = (blockIdx.x * blockDim.x + threadIdx.x) * 4;
    if (i >= n) return;
    float4 v = *reinterpret_cast<const float4*>(in + i);
    __nv_bfloat16 h0 = __float2bfloat16(v.x);
    __nv_bfloat16 h1 = __float2bfloat16(v.y);
    __nv_bfloat16 h2 = __float2bfloat16(v.z);
    __nv_bfloat16 h3 = __float2bfloat16(v.w);
    __nv_bfloat162 hh0 = {h0, h1}, hh1 = {h2, h3};
    *reinterpret_cast<__nv_bfloat162*>(hi + i)     = hh0;
    *reinterpret_cast<__nv_bfloat162*>(hi + i + 2) = hh1;
    __nv_bfloat162 ll0 = {__float2bfloat16(v.x - __bfloat162float(h0)),
                          __float2bfloat16(v.y - __bfloat162float(h1))};
    __nv_bfloat162 ll1 = {__float2bfloat16(v.z - __bfloat162float(h2)),
                          __float2bfloat16(v.w - __bfloat162float(h3))};
    *reinterpret_cast<__nv_bfloat162*>(lo + i)     = ll0;
    *reinterpret_cast<__nv_bfloat162*>(lo + i + 2) = ll1;
}

// in fp32 [R,C] -> hi/lo bf16 [C,R]
__global__ void tsplit_kernel(const float* __restrict__ in,
                              __nv_bfloat16* __restrict__ hi,
                              __nv_bfloat16* __restrict__ lo, int R, int C)
{
    __shared__ float tile[32][33];
    int c0 = blockIdx.x * 32, r0 = blockIdx.y * 32;
    int tx = threadIdx.x, ty = threadIdx.y;  // 32 x 8
#pragma unroll
    for (int j = 0; j < 32; j += 8)
        tile[ty + j][tx] = in[(size_t)(r0 + ty + j) * C + c0 + tx];
    __syncthreads();
#pragma unroll
    for (int j = 0; j < 32; j += 8) {
        float x = tile[tx][ty + j];
        __nv_bfloat16 h = __float2bfloat16(x);
        size_t o = (size_t)(c0 + ty + j) * R + r0 + tx;
        hi[o] = h;
        lo[o] = __float2bfloat16(x - __bfloat162float(h));
    }
}

// ==================== HMMA (mma.sync) fused 3-product split-K GEMM ====================
// C[M,N] fp32 row-major += Ahi*Bhi^T + Alo*Bhi^T + Ahi*Blo^T (all K-major bf16)
// M,N mult of 128; per-z K slice mult of 32. gridDim.z = split-K factor;
// z>1 requires C pre-zeroed (epilogue uses atomicAdd).
// SMEM: 2 buffers x 32KB. Each buffer: A tile 16KB + B tile 16KB.
// Tile row (128B, SW128-swizzled): k[0..31] hi (64B) | k[0..31] lo (64B).
#define GEMM_SMEM_BYTES 65536

__device__ __forceinline__ uint32_t smem_u32(const void* p) {
    uint32_t a;
    asm("{ .reg .u64 t; cvta.to.shared.u64 t, %1; cvt.u32.u64 %0, t; }" : "=r"(a) : "l"(p));
    return a;
}
__device__ __forceinline__ void cp_async16(uint32_t saddr, const void* gaddr) {
    asm volatile("cp.async.cg.shared.global [%0], [%1], 16;" :: "r"(saddr), "l"(gaddr));
}
__device__ __forceinline__ void cp_commit() {
    asm volatile("cp.async.commit_group;");
}
__device__ __forceinline__ void ldsm_x4(uint32_t* r, uint32_t addr) {
    asm volatile("ldmatrix.sync.aligned.m8n8.x4.shared.b16 {%0,%1,%2,%3}, [%4];"
        : "=r"(r[0]), "=r"(r[1]), "=r"(r[2]), "=r"(r[3]) : "r"(addr));
}
__device__ __forceinline__ void mma_bf16(float* d, const uint32_t* a, uint32_t b0, uint32_t b1) {
    asm volatile(
        "mma.sync.aligned.m16n8k16.row.col.f32.bf16.bf16.f32 "
        "{%0,%1,%2,%3}, {%4,%5,%6,%7}, {%8,%9}, {%0,%1,%2,%3};"
        : "+f"(d[0]), "+f"(d[1]), "+f"(d[2]), "+f"(d[3])
        : "r"(a[0]), "r"(a[1]), "r"(a[2]), "r"(a[3]), "r"(b0), "r"(b1));
}
__device__ __forceinline__ uint32_t sw128(uint32_t off) {
    return off ^ ((off >> 3) & 0x70);
}

__global__ __launch_bounds__(256, 2) void gemm_mma_kernel(
    const __nv_bfloat16* __restrict__ Ahi, const __nv_bfloat16* __restrict__ Alo,
    const __nv_bfloat16* __restrict__ Bhi, const __nv_bfloat16* __restrict__ Blo,
    float* __restrict__ C, int M, int N, int K)
{
    extern __shared__ char smem[];
    const uint32_t sbase = smem_u32(smem);
    const int tid = threadIdx.x, lane = tid & 31, wid = tid >> 5;
    const int bm = blockIdx.y * 128, bn = blockIdx.x * 128;
    const int wm = (wid >> 1) * 32;     // warp M offset: 0/32/64/96
    const int wn = (wid & 1) * 64;      // warp N offset: 0/64

    const int ksz = K / gridDim.z;      // this z-slice's K extent
    const int k0  = blockIdx.z * ksz;   // element offset along K
    const int nch = ksz >> 5;           // chunks of 32

    float acc[2][8][4];
#pragma unroll
    for (int mi = 0; mi < 2; mi++)
#pragma unroll
        for (int ni = 0; ni < 8; ni++)
#pragma unroll
            for (int q = 0; q < 4; q++) acc[mi][ni][q] = 0.f;

    // per-thread load slots: u in 0..1023 -> row 0..127, cb 0..7 (16B blocks)
    // cb 0..3 = hi halves (cols (cb)*8), cb 4..7 = lo halves (cols (cb-4)*8)
    int lrow[4], lcol[4];
    uint32_t lsw[4];
    bool lhi[4];
#pragma unroll
    for (int it = 0; it < 4; it++) {
        int u = tid + it * 256;
        lrow[it] = u >> 3;
        int cb   = u & 7;
        lhi[it]  = cb < 4;
        lcol[it] = (cb & 3) * 8;         // element offset within 32-wide chunk
        lsw[it]  = sw128((uint32_t)(lrow[it] * 128 + cb * 16));
    }

    // ldmatrix address components
    const int a_row = wm + (lane & 15);
    const int a_kof = (lane >> 4) * 8;
    const int b_row = wn + ((lane >> 4) << 3) + (lane & 7);
    const int b_kof = ((lane >> 3) & 1) * 8;

    auto issue = [&](int kc, int buf) {
        uint32_t sbuf = sbase + buf * 32768;
#pragma unroll
        for (int it = 0; it < 4; it++) {
            const __nv_bfloat16* PA = lhi[it] ? Ahi : Alo;
            const __nv_bfloat16* PB = lhi[it] ? Bhi : Blo;
            int col = k0 + kc * 32 + lcol[it];
            cp_async16(sbuf + lsw[it],         PA + (size_t)(bm + lrow[it]) * K + col);
            cp_async16(sbuf + 16384 + lsw[it], PB + (size_t)(bn + lrow[it]) * K + col);
        }
        cp_commit();
    };

    issue(0, 0);
    for (int g = 0; g < nch; g++) {
        if (g + 1 < nch) {
            issue(g + 1, (g + 1) & 1);
            asm volatile("cp.async.wait_group 1;" ::: "memory");
        } else {
            asm volatile("cp.async.wait_group 0;" ::: "memory");
        }
        __syncthreads();
        uint32_t sbuf = sbase + (g & 1) * 32768;
        const uint32_t sA = sbuf, sB = sbuf + 16384;
#pragma unroll
        for (int kk = 0; kk < 32; kk += 16) {
            uint32_t ah[2][4], al[2][4], bh[4][4], bl[4][4];
#pragma unroll
            for (int mi = 0; mi < 2; mi++) {
                uint32_t offh = (uint32_t)((a_row + mi * 16) * 128 + (kk + a_kof) * 2);
                ldsm_x4(ah[mi], sA + sw128(offh));
                ldsm_x4(al[mi], sA + sw128(offh + 64));
            }
#pragma unroll
            for (int np = 0; np < 4; np++) {
                uint32_t offh = (uint32_t)((b_row + np * 16) * 128 + (kk + b_kof) * 2);
                ldsm_x4(bh[np], sB + sw128(offh));
                ldsm_x4(bl[np], sB + sw128(offh + 64));
            }
#pragma unroll
            for (int mi = 0; mi < 2; mi++)
#pragma unroll
                for (int ni = 0; ni < 8; ni++) {
                    uint32_t b0h = bh[ni >> 1][(ni & 1) * 2], b1h = bh[ni >> 1][(ni & 1) * 2 + 1];
                    uint32_t b0l = bl[ni >> 1][(ni & 1) * 2], b1l = bl[ni >> 1][(ni & 1) * 2 + 1];
                    mma_bf16(acc[mi][ni], ah[mi], b0h, b1h);
                    mma_bf16(acc[mi][ni], al[mi], b0h, b1h);
                    mma_bf16(acc[mi][ni], ah[mi], b0l, b1l);
                }
        }
        __syncthreads();
    }

    // epilogue: m16n8 C fragment: rows lane>>2 (+8), cols (lane&3)*2 (+1)
    const int er = lane >> 2, ec = (lane & 3) * 2;
    if (gridDim.z == 1) {
#pragma unroll
        for (int mi = 0; mi < 2; mi++) {
            int row0 = bm + wm + mi * 16 + er;
#pragma unroll
            for (int ni = 0; ni < 8; ni++) {
                int col = bn + wn + ni * 8 + ec;
                *reinterpret_cast<float2*>(C + (size_t)row0 * N + col) =
                    make_float2(acc[mi][ni][0], acc[mi][ni][1]);
                *reinterpret_cast<float2*>(C + (size_t)(row0 + 8) * N + col) =
                    make_float2(acc[mi][ni][2], acc[mi][ni][3]);
            }
        }
    } else {
#pragma unroll
        for (int mi = 0; mi < 2; mi++) {
            int row0 = bm + wm + mi * 16 + er;
#pragma unroll
            for (int ni = 0; ni < 8; ni++) {
                int col = bn + wn + ni * 8 + ec;
                atomicAdd(C + (size_t)row0 * N + col,       acc[mi][ni][0]);
                atomicAdd(C + (size_t)row0 * N + col + 1,   acc[mi][ni][1]);
                atomicAdd(C + (size_t)(row0 + 8) * N + col,     acc[mi][ni][2]);
                atomicAdd(C + (size_t)(row0 + 8) * N + col + 1, acc[mi][ni][3]);
            }
        }
    }
}

// ==================== sparse aggregation ====================
__global__ void gcn_agg_kernel(const float* __restrict__ xw, const float* __restrict__ bias,
                               float* __restrict__ out, int F, int do_tanh)
{
    int v = blockIdx.x, f = threadIdx.x;
    __shared__ int   sid[256];
    __shared__ float snw[256];
    int nb = d_cnt_in[v], base = d_off_in[v];
    float dv = d_dis_sp[v];
    float acc = 0.f;
    int CH = blockDim.x;
    for (int c0 = 0; c0 < nb; c0 += CH) {
        int m = min(CH, nb - c0);
        __syncthreads();
        if (f < m) {
            int r = d_csc_src[base + c0 + f];
            sid[f] = r;
            snw[f] = d_dis_sp[r];
        }
        __syncthreads();
#pragma unroll 4
        for (int e = 0; e < m; e++)
            acc += snw[e] * xw[(size_t)sid[e] * F + f];
    }
    float o = dv * acc + dv * dv * xw[(size_t)v * F + f] + bias[f];
    out[(size_t)v * F + f] = do_tanh ? tanhf(o) : o;
}

__global__ void s_agg_kernel(const float* __restrict__ xwp, const float* __restrict__ bp,
                             float* __restrict__ s)
{
    int v = blockIdx.x, t = threadIdx.x;
    __shared__ int   sid[256];
    __shared__ float snw[256];
    int nb = d_cnt_out[v], base = d_off_out[v];
    float dv = d_dis_dn[v];
    float a0 = 0.f, a1 = 0.f, a2 = 0.f, a3 = 0.f;
    for (int c0 = 0; c0 < nb; c0 += 256) {
        int m = min(256, nb - c0);
        __syncthreads();
        if (t < m) {
            int c = d_csr_dst[base + c0 + t];
            sid[t] = c;
            snw[t] = (c == v) ? 0.f : d_dis_dn[c];
        }
        __syncthreads();
#pragma unroll 4
        for (int e = 0; e < m; e++) {
            float w = snw[e];
            const float* xr = xwp + (size_t)sid[e] * KCL;
            a0 += w * xr[t];       a1 += w * xr[t + 256];
            a2 += w * xr[t + 512]; a3 += w * xr[t + 768];
        }
    }
    const float* xv = xwp + (size_t)v * KCL;
    float dvv = dv * dv;
    s[(size_t)v * KCL + t]       = dv * a0 + dvv * xv[t]       + bp[t];
    s[(size_t)v * KCL + t + 256] = dv * a1 + dvv * xv[t + 256] + bp[t + 256];
    s[(size_t)v * KCL + t + 512] = dv * a2 + dvv * xv[t + 512] + bp[t + 512];
    s[(size_t)v * KCL + t + 768] = dv * a3 + dvv * xv[t + 768] + bp[t + 768];
}

__global__ void t_agg_kernel(const float* __restrict__ ss, float* __restrict__ tt)
{
    int v = blockIdx.x, t = threadIdx.x;
    __shared__ int sid[256];
    int nb = d_cnt_out[v], base = d_off_out[v];
    float a0 = 0.f, a1 = 0.f, a2 = 0.f, a3 = 0.f;
    for (int c0 = 0; c0 < nb; c0 += 256) {
        int m = min(256, nb - c0);
        __syncthreads();
        if (t < m) sid[t] = d_csr_dst[base + c0 + t];
        __syncthreads();
#pragma unroll 4
        for (int e = 0; e < m; e++) {
            const float* xr = ss + (size_t)sid[e] * KCL;
            a0 += xr[t];       a1 += xr[t + 256];
            a2 += xr[t + 512]; a3 += xr[t + 768];
        }
    }
    tt[(size_t)v * KCL + t]       = a0;
    tt[(size_t)v * KCL + t + 256] = a1;
    tt[(size_t)v * KCL + t + 512] = a2;
    tt[(size_t)v * KCL + t + 768] = a3;
}

__global__ void softmax_ent_kernel(float* __restrict__ s)
{
    int v = blockIdx.x, t = threadIdx.x;
    float* row = s + (size_t)v * KCL;
    float x0 = row[t], x1 = row[t + 256], x2 = row[t + 512], x3 = row[t + 768];
    __shared__ float red[256];
    float mx = fmaxf(fmaxf(x0, x1), fmaxf(x2, x3));
    red[t] = mx; __syncthreads();
    for (int o = 128; o > 0; o >>= 1) { if (t < o) red[t] = fmaxf(red[t], red[t + o]); __syncthreads(); }
    float m = red[0]; __syncthreads();
    float e0 = expf(x0 - m), e1 = expf(x1 - m), e2 = expf(x2 - m), e3 = expf(x3 - m);
    red[t] = e0 + e1 + e2 + e3; __syncthreads();
    for (int o = 128; o > 0; o >>= 1) { if (t < o) red[t] += red[t + o]; __syncthreads(); }
    float inv = 1.0f / red[0]; __syncthreads();
    float p0 = e0 * inv, p1 = e1 * inv, p2 = e2 * inv, p3 = e3 * inv;
    row[t] = p0; row[t + 256] = p1; row[t + 512] = p2; row[t + 768] = p3;
    float ent = -(p0 * logf(p0 + 1e-15f) + p1 * logf(p1 + 1e-15f) +
                  p2 * logf(p2 + 1e-15f) + p3 * logf(p3 + 1e-15f));
    red[t] = ent; __syncthreads();
    for (int o = 128; o > 0; o >>= 1) { if (t < o) red[t] += red[t + o]; __syncthreads(); }
    if (t == 0) atomicAdd(&d_scal[0], (double)red[0]);
}

// dot product of two big arrays -> d_scal[slot]  (cross = <A S, S> = <t, s>)
__global__ void dot_kernel(const float* __restrict__ a, const float* __restrict__ b,
                           int n, int slot)
{
    int i = (blockIdx.x * blockDim.x + threadIdx.x) * 4;
    float p = 0.f;
    int stride = gridDim.x * blockDim.x * 4;
    for (; i < n; i += stride) {
        float4 va = *reinterpret_cast<const float4*>(a + i);
        float4 vb = *reinterpret_cast<const float4*>(b + i);
        p += va.x * vb.x + va.y * vb.y + va.z * vb.z + va.w * vb.w;
    }
    __shared__ float red[256];
    red[threadIdx.x] = p; __syncthreads();
    for (int o = 128; o > 0; o >>= 1) { if (threadIdx.x < o) red[threadIdx.x] += red[threadIdx.x + o]; __syncthreads(); }
    if (threadIdx.x == 0) atomicAdd(&d_scal[slot], (double)red[0]);
}

__global__ void dupsq_kernel()
{
    int v = blockIdx.x, t = threadIdx.x;
    int nb = d_cnt_out[v], base = d_off_out[v];
    int tot = 0;
    for (int i = t; i < nb; i += blockDim.x) {
        int ci = d_csr_dst[base + i];
        int c = 0;
        for (int j = 0; j < nb; j++) c += (d_csr_dst[base + j] == ci) ? 1 : 0;
        tot += c;
    }
    __shared__ int red[256];
    red[t] = tot; __syncthreads();
    for (int o = 128; o > 0; o >>= 1) { if (t < o) red[t] += red[t + o]; __syncthreads(); }
    if (t == 0 && red[0] != 0) atomicAdd(&d_scal[2], (double)red[0]);
}

__global__ void sq_reduce_kernel(const float* __restrict__ a, int n, int slot)
{
    int i = blockIdx.x * blockDim.x + threadIdx.x;
    float p = 0.f;
    for (; i < n; i += gridDim.x * blockDim.x) { float x = a[i]; p += x * x; }
    __shared__ float red[256];
    red[threadIdx.x] = p; __syncthreads();
    for (int o = 128; o > 0; o >>= 1) { if (threadIdx.x < o) red[threadIdx.x] += red[threadIdx.x + o]; __syncthreads(); }
    if (threadIdx.x == 0) atomicAdd(&d_scal[slot], (double)red[0]);
}

__global__ void finalize_kernel(float* __restrict__ out_link, float* __restrict__ out_ent)
{
    double v = d_scal[2] - 2.0 * d_scal[1] + d_scal[3];
    if (v < 0.0) v = 0.0;
    *out_link = (float)(0.1 * sqrt(v) / ((double)N_NODES * (double)N_NODES));
    *out_ent  = (float)(0.1 * (d_scal[0] / (double)N_NODES));
}

// ==================== host side ====================
static void gemm_tc(const __nv_bfloat16* Ah, const __nv_bfloat16* Al,
                    const __nv_bfloat16* Bh, const __nv_bfloat16* Bl,
                    float* C, int M, int N, int K, int SK)
{
    static int attr_done = 0;
    if (!attr_done) {
        cudaFuncSetAttribute(gemm_mma_kernel, cudaFuncAttributeMaxDynamicSharedMemorySize,
                             GEMM_SMEM_BYTES);
        attr_done = 1;
    }
    if (SK > 1)
        zero_kernel<<<((M * N) / 4 + 255) / 256, 256>>>(C, M * N);
    gemm_mma_kernel<<<dim3(N / 128, M / 128, SK), 256, GEMM_SMEM_BYTES>>>(Ah, Al, Bh, Bl, C, M, N, K);
}
static void split_f(const float* in, __nv_bfloat16* hi, __nv_bfloat16* lo, int n)
{
    split_kernel<<<(n / 4 + 255) / 256, 256>>>(in, hi, lo, n);
}
static void tsplit_f(const float* in, __nv_bfloat16* hi, __nv_bfloat16* lo, int R, int C)
{
    tsplit_kernel<<<dim3(C / 32, R / 32), dim3(32, 8)>>>(in, hi, lo, R, C);
}

extern "C" void kernel_launch(void* const* d_in, const int* in_sizes, int n_in,
                              void* d_out, int out_size)
{
    const float* nodes = (const float*)d_in[0];
    const int*   ei    = (const int*)d_in[1];
    const float* W1 = (const float*)d_in[3];  const float* b1 = (const float*)d_in[4];
    const float* W2 = (const float*)d_in[5];  const float* b2 = (const float*)d_in[6];
    const float* Wp = (const float*)d_in[7];  const float* bp = (const float*)d_in[8];
    const float* W3 = (const float*)d_in[9];  const float* b3 = (const float*)d_in[10];
    const float* W4 = (const float*)d_in[11]; const float* b4 = (const float*)d_in[12];
    const float* W5 = (const float*)d_in[13]; const float* b5 = (const float*)d_in[14];
    int E = in_sizes[1] / 2;

    float* out      = (float*)d_out;
    float* out_x    = out;
    float* out_adj  = out + (size_t)N_NODES * FEAT;
    float* out_link = out + (size_t)N_NODES * FEAT + (size_t)N_NODES * N_NODES;
    float* out_ent  = out_link + 1;

    float *x1, *x2, *xw, *s, *t, *Mb, *xp, *adjp, *G, *xo;
    cudaGetSymbolAddress((void**)&x1,   g_x1);
    cudaGetSymbolAddress((void**)&x2,   g_x2);
    cudaGetSymbolAddress((void**)&xw,   g_xw);
    cudaGetSymbolAddress((void**)&s,    g_s);
    cudaGetSymbolAddress((void**)&t,    g_t);
    cudaGetSymbolAddress((void**)&Mb,   g_M);
    cudaGetSymbolAddress((void**)&xp,   g_xp);
    cudaGetSymbolAddress((void**)&adjp, g_adjp);
    cudaGetSymbolAddress((void**)&G,    g_G);
    cudaGetSymbolAddress((void**)&xo,   g_xo);

    __nv_bfloat16 *nhi,*nlo,*xhi,*xlo,*wthi,*wtlo,*shi,*slo,*sthi,*stlo;
    __nv_bfloat16 *x2thi,*x2tlo,*tthi,*ttlo,*xpthi,*xptlo,*apthi,*aptlo,*mbhi,*mblo;
    cudaGetSymbolAddress((void**)&nhi,  g_nhi);  cudaGetSymbolAddress((void**)&nlo,  g_nlo);
    cudaGetSymbolAddress((void**)&xhi,  g_xhi);  cudaGetSymbolAddress((void**)&xlo,  g_xlo);
    cudaGetSymbolAddress((void**)&wthi, g_wthi); cudaGetSymbolAddress((void**)&wtlo, g_wtlo);
    cudaGetSymbolAddress((void**)&shi,  g_shi);  cudaGetSymbolAddress((void**)&slo,  g_slo);
    cudaGetSymbolAddress((void**)&sthi, g_sthi); cudaGetSymbolAddress((void**)&stlo, g_stlo);
    cudaGetSymbolAddress((void**)&x2thi,g_x2thi);cudaGetSymbolAddress((void**)&x2tlo,g_x2tlo);
    cudaGetSymbolAddress((void**)&tthi, g_tthi); cudaGetSymbolAddress((void**)&ttlo, g_ttlo);
    cudaGetSymbolAddress((void**)&xpthi,g_xpthi);cudaGetSymbolAddress((void**)&xptlo,g_xptlo);
    cudaGetSymbolAddress((void**)&apthi,g_apthi);cudaGetSymbolAddress((void**)&aptlo,g_aptlo);
    cudaGetSymbolAddress((void**)&mbhi, g_mbhi); cudaGetSymbolAddress((void**)&mblo, g_mblo);

    // graph preprocessing
    init_zero_kernel<<<(N_NODES + 255) / 256, 256>>>();
    count_kernel<<<(E + 255) / 256, 256>>>(ei, E);
    scan_kernel<<<1, 1024>>>();
    fill_kernel<<<(E + 255) / 256, 256>>>(ei, E);

    // ---- encoder ----
    split_f(nodes, nhi, nlo, N_NODES * FEAT);
    tsplit_f(W1, wthi, wtlo, FEAT, HID);                     // [HID, FEAT]
    gemm_tc(nhi, nlo, wthi, wtlo, xw, N_NODES, HID, FEAT, 2);
    gcn_agg_kernel<<<N_NODES, HID>>>(xw, b1, x1, HID, 1);

    split_f(x1, xhi, xlo, N_NODES * HID);
    tsplit_f(W2, wthi, wtlo, HID, HID);
    gemm_tc(xhi, xlo, wthi, wtlo, xw, N_NODES, HID, HID, 4);
    gcn_agg_kernel<<<N_NODES, HID>>>(xw, b2, x2, HID, 1);

    // ---- assignment ----
    split_f(x2, xhi, xlo, N_NODES * HID);
    tsplit_f(Wp, wthi, wtlo, HID, KCL);                      // [KCL, HID]
    gemm_tc(xhi, xlo, wthi, wtlo, xw, N_NODES, KCL, HID, 1);
    s_agg_kernel<<<N_NODES, 256>>>(xw, bp, s);
    softmax_ent_kernel<<<N_NODES, 256>>>(s);

    // ---- pooling ----
    split_f(s, shi, slo, N_NODES * KCL);
    tsplit_f(s, sthi, stlo, N_NODES, KCL);                   // S^T [KCL, N]
    tsplit_f(x2, x2thi, x2tlo, N_NODES, HID);                // x2^T [HID, N]
    gemm_tc(sthi, stlo, x2thi, x2tlo, xp, KCL, HID, N_NODES, 16); // xp = S^T x2
    t_agg_kernel<<<N_NODES, 256>>>(s, t);                    // t = A S
    tsplit_f(t, tthi, ttlo, N_NODES, KCL);                   // t^T [KCL, N]
    gemm_tc(sthi, stlo, tthi, ttlo, adjp, KCL, KCL, N_NODES, 4);  // adjp = S^T A S
    gemm_tc(sthi, stlo, sthi, stlo, G, KCL, KCL, N_NODES, 4);     // G = S^T S

    // link-loss pieces: cross = <A S, S> = <t, s>
    dot_kernel<<<1024, 256>>>(t, s, N_NODES * KCL, 1);
    dupsq_kernel<<<N_NODES, 256>>>();
    sq_reduce_kernel<<<1024, 256>>>(G, KCL * KCL, 3);

    // ---- un-pool ----
    tsplit_f(xp, xpthi, xptlo, KCL, HID);                    // xp^T [HID, KCL]
    gemm_tc(shi, slo, xpthi, xptlo, xo, N_NODES, HID, KCL, 4);    // xo = S xp
    tsplit_f(adjp, apthi, aptlo, KCL, KCL);                  // adjp^T
    gemm_tc(shi, slo, apthi, aptlo, Mb, N_NODES, KCL, KCL, 1);    // Mb = S adjp
    split_f(Mb, mbhi, mblo, N_NODES * KCL);
    gemm_tc(mbhi, mblo, shi, slo, out_adj, N_NODES, N_NODES, KCL, 1); // adj_out = Mb S^T

    // ---- decoder ----
    split_f(xo, xhi, xlo, N_NODES * HID);
    tsplit_f(W3, wthi, wtlo, HID, HID);
    gemm_tc(xhi, xlo, wthi, wtlo, xw, N_NODES, HID, HID, 4);
    gcn_agg_kernel<<<N_NODES, HID>>>(xw, b3, x1, HID, 1);

    split_f(x1, xhi, xlo, N_NODES * HID);
    tsplit_f(W4, wthi, wtlo, HID, HID);
    gemm_tc(xhi, xlo, wthi, wtlo, xw, N_NODES, HID, HID, 4);
    gcn_agg_kernel<<<N_NODES, HID>>>(xw, b4, x2, HID, 1);

    split_f(x2, xhi, xlo, N_NODES * HID);
    tsplit_f(W5, wthi, wtlo, HID, FEAT);                     // [FEAT, HID]
    gemm_tc(xhi, xlo, wthi, wtlo, xw, N_NODES, FEAT, HID, 4);
    gcn_agg_kernel<<<N_NODES, FEAT>>>(xw, b5, out_x, FEAT, 0);

    // scalars
    finalize_kernel<<<1, 1>>>(out_link, out_ent);
}

// round 9
// speedup vs baseline: 1.5376x; 1.5376x over previous
#include <cuda_runtime.h>
#include <cuda_bf16.h>
#include <math.h>
#include <stdint.h>

// Problem constants (fixed for this dataset)
#define N_NODES 4096
#define FEAT    128
#define HID     256
#define KCL     1024
#define NE      131072

// ==================== device scratch ====================
__device__ __align__(16) int   d_cnt_in [N_NODES];
__device__ __align__(16) int   d_cnt_out[N_NODES];
__device__ __align__(16) int   d_selfc  [N_NODES];
__device__ __align__(16) int   d_cur_in [N_NODES];
__device__ __align__(16) int   d_cur_out[N_NODES];
__device__ __align__(16) int   d_off_in [N_NODES];
__device__ __align__(16) int   d_off_out[N_NODES];
__device__ __align__(16) int   d_csc_src[NE];
__device__ __align__(16) int   d_csr_dst[NE];
__device__ __align__(16) float d_dis_sp [N_NODES];
__device__ __align__(16) float d_dis_dn [N_NODES];
__device__ double d_scal[4];   // [0]=ent [1]=cross [2]=sum adj^2 [3]=||G||^2

__device__ __align__(16) float g_x1 [N_NODES*HID];
__device__ __align__(16) float g_x2 [N_NODES*HID];
__device__ __align__(16) float g_xw [N_NODES*KCL];
__device__ __align__(16) float g_s  [N_NODES*KCL];
__device__ __align__(16) float g_t  [N_NODES*KCL];
__device__ __align__(16) float g_M  [N_NODES*KCL];
__device__ __align__(16) float g_xp [KCL*HID];
__device__ __align__(16) float g_adjp[KCL*KCL];
__device__ __align__(16) float g_G  [KCL*KCL];
__device__ __align__(16) float g_xo [N_NODES*HID];

// bf16 split operand buffers
__device__ __align__(16) __nv_bfloat16 g_nhi [N_NODES*FEAT],  g_nlo [N_NODES*FEAT];
__device__ __align__(16) __nv_bfloat16 g_xhi [N_NODES*HID],   g_xlo [N_NODES*HID];
__device__ __align__(16) __nv_bfloat16 g_wthi[KCL*HID],       g_wtlo[KCL*HID];
__device__ __align__(16) __nv_bfloat16 g_shi [N_NODES*KCL],   g_slo [N_NODES*KCL];
__device__ __align__(16) __nv_bfloat16 g_sthi[KCL*N_NODES],   g_stlo[KCL*N_NODES];
__device__ __align__(16) __nv_bfloat16 g_x2thi[HID*N_NODES],  g_x2tlo[HID*N_NODES];
__device__ __align__(16) __nv_bfloat16 g_tthi[KCL*N_NODES],   g_ttlo[KCL*N_NODES];
__device__ __align__(16) __nv_bfloat16 g_xpthi[HID*KCL],      g_xptlo[HID*KCL];
__device__ __align__(16) __nv_bfloat16 g_apthi[KCL*KCL],      g_aptlo[KCL*KCL];
__device__ __align__(16) __nv_bfloat16 g_mbhi[N_NODES*KCL],   g_mblo[N_NODES*KCL];

// ==================== setup kernels ====================
__global__ void init_zero_kernel() {
    int i = blockIdx.x * blockDim.x + threadIdx.x;
    if (i < N_NODES) {
        d_cnt_in[i] = 0; d_cnt_out[i] = 0; d_selfc[i] = 0;
        d_cur_in[i] = 0; d_cur_out[i] = 0;
    }
    if (i < 4) d_scal[i] = 0.0;
}

__global__ void zero_kernel(float* __restrict__ p, int n) {
    int i = (blockIdx.x * blockDim.x + threadIdx.x) * 4;
    if (i < n) *reinterpret_cast<float4*>(p + i) = make_float4(0.f, 0.f, 0.f, 0.f);
}

__global__ void count_kernel(const int* __restrict__ ei, int E) {
    int e = blockIdx.x * blockDim.x + threadIdx.x;
    if (e >= E) return;
    int r = ei[e];
    int c = ei[E + e];
    atomicAdd(&d_cnt_out[r], 1);
    atomicAdd(&d_cnt_in[c], 1);
    if (r == c) atomicAdd(&d_selfc[r], 1);
}

__global__ void scan_kernel() {
    __shared__ int sh[1024];
    int t = threadIdx.x;
    {
        int v = t * 4;
        int a0 = d_cnt_in[v], a1 = d_cnt_in[v+1], a2 = d_cnt_in[v+2], a3 = d_cnt_in[v+3];
        int tot = a0 + a1 + a2 + a3;
        sh[t] = tot; __syncthreads();
        for (int o = 1; o < 1024; o <<= 1) {
            int x = (t >= o) ? sh[t - o] : 0;
            __syncthreads();
            sh[t] += x;
            __syncthreads();
        }
        int excl = sh[t] - tot;
        d_off_in[v]   = excl;
        d_off_in[v+1] = excl + a0;
        d_off_in[v+2] = excl + a0 + a1;
        d_off_in[v+3] = excl + a0 + a1 + a2;
        d_dis_sp[v]   = rsqrtf((float)(a0 + 1));
        d_dis_sp[v+1] = rsqrtf((float)(a1 + 1));
        d_dis_sp[v+2] = rsqrtf((float)(a2 + 1));
        d_dis_sp[v+3] = rsqrtf((float)(a3 + 1));
        __syncthreads();
    }
    {
        int v = t * 4;
        int a0 = d_cnt_out[v], a1 = d_cnt_out[v+1], a2 = d_cnt_out[v+2], a3 = d_cnt_out[v+3];
        int tot = a0 + a1 + a2 + a3;
        sh[t] = tot; __syncthreads();
        for (int o = 1; o < 1024; o <<= 1) {
            int x = (t >= o) ? sh[t - o] : 0;
            __syncthreads();
            sh[t] += x;
            __syncthreads();
        }
        int excl = sh[t] - tot;
        d_off_out[v]   = excl;
        d_off_out[v+1] = excl + a0;
        d_off_out[v+2] = excl + a0 + a1;
        d_off_out[v+3] = excl + a0 + a1 + a2;
        d_dis_dn[v]   = rsqrtf((float)(a0 - d_selfc[v]   + 1));
        d_dis_dn[v+1] = rsqrtf((float)(a1 - d_selfc[v+1] + 1));
        d_dis_dn[v+2] = rsqrtf((float)(a2 - d_selfc[v+2] + 1));
        d_dis_dn[v+3] = rsqrtf((float)(a3 - d_selfc[v+3] + 1));
    }
}

__global__ void fill_kernel(const int* __restrict__ ei, int E) {
    int e = blockIdx.x * blockDim.x + threadIdx.x;
    if (e >= E) return;
    int r = ei[e];
    int c = ei[E + e];
    int p = atomicAdd(&d_cur_in[c], 1);
    d_csc_src[d_off_in[c] + p] = r;
    int q = atomicAdd(&d_cur_out[r], 1);
    d_csr_dst[d_off_out[r] + q] = c;
}

// ==================== split / transpose-split ====================
__global__ void split_kernel(const float* __restrict__ in,
                             __nv_bfloat16* __restrict__ hi,
                             __nv_bfloat16* __restrict__ lo, int n)
{
    int i = (blockIdx.x * blockDim.x + threadIdx.x) * 4;
    if (i >= n) return;
    float4 v = *reinterpret_cast<const float4*>(in + i);
    __nv_bfloat16 h0 = __float2bfloat16(v.x);
    __nv_bfloat16 h1 = __float2bfloat16(v.y);
    __nv_bfloat16 h2 = __float2bfloat16(v.z);
    __nv_bfloat16 h3 = __float2bfloat16(v.w);
    __nv_bfloat162 hh0 = {h0, h1}, hh1 = {h2, h3};
    *reinterpret_cast<__nv_bfloat162*>(hi + i)     = hh0;
    *reinterpret_cast<__nv_bfloat162*>(hi + i + 2) = hh1;
    __nv_bfloat162 ll0 = {__float2bfloat16(v.x - __bfloat162float(h0)),
                          __float2bfloat16(v.y - __bfloat162float(h1))};
    __nv_bfloat162 ll1 = {__float2bfloat16(v.z - __bfloat162float(h2)),
                          __float2bfloat16(v.w - __bfloat162float(h3))};
    *reinterpret_cast<__nv_bfloat162*>(lo + i)     = ll0;
    *reinterpret_cast<__nv_bfloat162*>(lo + i + 2) = ll1;
}

// in fp32 [R,C] -> hi/lo bf16 [C,R]
__global__ void tsplit_kernel(const float* __restrict__ in,
                              __nv_bfloat16* __restrict__ hi,
                              __nv_bfloat16* __restrict__ lo, int R, int C)
{
    __shared__ float tile[32][33];
    int c0 = blockIdx.x * 32, r0 = blockIdx.y * 32;
    int tx = threadIdx.x, ty = threadIdx.y;  // 32 x 8
#pragma unroll
    for (int j = 0; j < 32; j += 8)
        tile[ty + j][tx] = in[(size_t)(r0 + ty + j) * C + c0 + tx];
    __syncthreads();
#pragma unroll
    for (int j = 0; j < 32; j += 8) {
        float x = tile[tx][ty + j];
        __nv_bfloat16 h = __float2bfloat16(x);
        size_t o = (size_t)(c0 + ty + j) * R + r0 + tx;
        hi[o] = h;
        lo[o] = __float2bfloat16(x - __bfloat162float(h));
    }
}

// ==================== HMMA common helpers ====================
__device__ __forceinline__ uint32_t smem_u32(const void* p) {
    uint32_t a;
    asm("{ .reg .u64 t; cvta.to.shared.u64 t, %1; cvt.u32.u64 %0, t; }" : "=r"(a) : "l"(p));
    return a;
}
__device__ __forceinline__ void cp_async16(uint32_t saddr, const void* gaddr) {
    asm volatile("cp.async.cg.shared.global [%0], [%1], 16;" :: "r"(saddr), "l"(gaddr));
}
__device__ __forceinline__ void cp_commit() {
    asm volatile("cp.async.commit_group;");
}
__device__ __forceinline__ void ldsm_x4(uint32_t* r, uint32_t addr) {
    asm volatile("ldmatrix.sync.aligned.m8n8.x4.shared.b16 {%0,%1,%2,%3}, [%4];"
        : "=r"(r[0]), "=r"(r[1]), "=r"(r[2]), "=r"(r[3]) : "r"(addr));
}
__device__ __forceinline__ void mma_bf16(float* d, const uint32_t* a, uint32_t b0, uint32_t b1) {
    asm volatile(
        "mma.sync.aligned.m16n8k16.row.col.f32.bf16.bf16.f32 "
        "{%0,%1,%2,%3}, {%4,%5,%6,%7}, {%8,%9}, {%0,%1,%2,%3};"
        : "+f"(d[0]), "+f"(d[1]), "+f"(d[2]), "+f"(d[3])
        : "r"(a[0]), "r"(a[1]), "r"(a[2]), "r"(a[3]), "r"(b0), "r"(b1));
}
__device__ __forceinline__ uint32_t sw128(uint32_t off) {
    return off ^ ((off >> 3) & 0x70);
}

// ==================== 3-term fused split GEMM (R6 config) ====================
// C[M,N] fp32 row-major (+)= Ahi*Bhi^T + Alo*Bhi^T + Ahi*Blo^T (K-major bf16).
// M,N mult of 128; per-z K slice mult of 64.  SMEM: 2 bufs x [Ahi|Alo|Bhi|Blo] x 16KB.
#define GEMM3_SMEM_BYTES 131072

__global__ __launch_bounds__(256) void gemm3_mma_kernel(
    const __nv_bfloat16* __restrict__ Ahi, const __nv_bfloat16* __restrict__ Alo,
    const __nv_bfloat16* __restrict__ Bhi, const __nv_bfloat16* __restrict__ Blo,
    float* __restrict__ C, int M, int N, int K)
{
    extern __shared__ char smem[];
    const uint32_t sbase = smem_u32(smem);
    const int tid = threadIdx.x, lane = tid & 31, wid = tid >> 5;
    const int bm = blockIdx.y * 128, bn = blockIdx.x * 128;
    const int wm = (wid >> 1) * 32;
    const int wn = (wid & 1) * 64;

    const int ksz = K / gridDim.z;
    const int k0  = blockIdx.z * ksz;
    const int nch = ksz >> 6;

    float acc[2][8][4];
#pragma unroll
    for (int mi = 0; mi < 2; mi++)
#pragma unroll
        for (int ni = 0; ni < 8; ni++)
#pragma unroll
            for (int q = 0; q < 4; q++) acc[mi][ni][q] = 0.f;

    int lrow[4], lcb[4];
    uint32_t lsw[4];
#pragma unroll
    for (int it = 0; it < 4; it++) {
        int u = tid + it * 256;
        lrow[it] = u >> 3;
        lcb[it]  = u & 7;
        lsw[it]  = sw128((uint32_t)(lrow[it] * 128 + lcb[it] * 16));
    }

    const int a_row = wm + (lane & 15);
    const int a_kof = (lane >> 4) * 8;
    const int b_row = wn + ((lane >> 4) << 3) + (lane & 7);
    const int b_kof = ((lane >> 3) & 1) * 8;

    auto issue = [&](int kc, int buf) {
        uint32_t sbuf = sbase + buf * 65536;
        const __nv_bfloat16* tp[4] = { Ahi, Alo, Bhi, Blo };
#pragma unroll
        for (int tI = 0; tI < 4; tI++) {
            int ro = (tI < 2) ? bm : bn;
            const __nv_bfloat16* P = tp[tI];
            uint32_t sdst = sbuf + tI * 16384;
#pragma unroll
            for (int it = 0; it < 4; it++)
                cp_async16(sdst + lsw[it],
                           P + (size_t)(ro + lrow[it]) * K + k0 + kc * 64 + lcb[it] * 8);
        }
        cp_commit();
    };

    issue(0, 0);
    for (int g = 0; g < nch; g++) {
        if (g + 1 < nch) {
            issue(g + 1, (g + 1) & 1);
            asm volatile("cp.async.wait_group 1;" ::: "memory");
        } else {
            asm volatile("cp.async.wait_group 0;" ::: "memory");
        }
        __syncthreads();
        uint32_t sbuf = sbase + (g & 1) * 65536;
        const uint32_t sAh = sbuf, sAl = sbuf + 16384, sBh = sbuf + 32768, sBl = sbuf + 49152;
#pragma unroll
        for (int kk = 0; kk < 64; kk += 16) {
            uint32_t ah[2][4], al[2][4], bh[4][4], bl[4][4];
#pragma unroll
            for (int mi = 0; mi < 2; mi++) {
                uint32_t off = sw128((uint32_t)((a_row + mi * 16) * 128 + (kk + a_kof) * 2));
                ldsm_x4(ah[mi], sAh + off);
                ldsm_x4(al[mi], sAl + off);
            }
#pragma unroll
            for (int np = 0; np < 4; np++) {
                uint32_t off = sw128((uint32_t)((b_row + np * 16) * 128 + (kk + b_kof) * 2));
                ldsm_x4(bh[np], sBh + off);
                ldsm_x4(bl[np], sBl + off);
            }
#pragma unroll
            for (int mi = 0; mi < 2; mi++)
#pragma unroll
                for (int ni = 0; ni < 8; ni++) {
                    uint32_t b0h = bh[ni >> 1][(ni & 1) * 2], b1h = bh[ni >> 1][(ni & 1) * 2 + 1];
                    uint32_t b0l = bl[ni >> 1][(ni & 1) * 2], b1l = bl[ni >> 1][(ni & 1) * 2 + 1];
                    mma_bf16(acc[mi][ni], ah[mi], b0h, b1h);
                    mma_bf16(acc[mi][ni], al[mi], b0h, b1h);
                    mma_bf16(acc[mi][ni], ah[mi], b0l, b1l);
                }
        }
        __syncthreads();
    }

    const int er = lane >> 2, ec = (lane & 3) * 2;
    if (gridDim.z == 1) {
#pragma unroll
        for (int mi = 0; mi < 2; mi++) {
            int row0 = bm + wm + mi * 16 + er;
#pragma unroll
            for (int ni = 0; ni < 8; ni++) {
                int col = bn + wn + ni * 8 + ec;
                *reinterpret_cast<float2*>(C + (size_t)row0 * N + col) =
                    make_float2(acc[mi][ni][0], acc[mi][ni][1]);
                *reinterpret_cast<float2*>(C + (size_t)(row0 + 8) * N + col) =
                    make_float2(acc[mi][ni][2], acc[mi][ni][3]);
            }
        }
    } else {
#pragma unroll
        for (int mi = 0; mi < 2; mi++) {
            int row0 = bm + wm + mi * 16 + er;
#pragma unroll
            for (int ni = 0; ni < 8; ni++) {
                int col = bn + wn + ni * 8 + ec;
                atomicAdd(C + (size_t)row0 * N + col,       acc[mi][ni][0]);
                atomicAdd(C + (size_t)row0 * N + col + 1,   acc[mi][ni][1]);
                atomicAdd(C + (size_t)(row0 + 8) * N + col,     acc[mi][ni][2]);
                atomicAdd(C + (size_t)(row0 + 8) * N + col + 1, acc[mi][ni][3]);
            }
        }
    }
}

// ==================== 1-term plain bf16 GEMM (positive chains) ====================
// C[M,N] fp32 row-major (+)= A*B^T (K-major bf16). SMEM: 2 bufs x [A|B] x 16KB.
#define GEMM1_SMEM_BYTES 65536

__global__ __launch_bounds__(256) void gemm1_mma_kernel(
    const __nv_bfloat16* __restrict__ A, const __nv_bfloat16* __restrict__ B,
    float* __restrict__ C, int M, int N, int K)
{
    extern __shared__ char smem[];
    const uint32_t sbase = smem_u32(smem);
    const int tid = threadIdx.x, lane = tid & 31, wid = tid >> 5;
    const int bm = blockIdx.y * 128, bn = blockIdx.x * 128;
    const int wm = (wid >> 1) * 32;
    const int wn = (wid & 1) * 64;

    const int ksz = K / gridDim.z;
    const int k0  = blockIdx.z * ksz;
    const int nch = ksz >> 6;

    float acc[2][8][4];
#pragma unroll
    for (int mi = 0; mi < 2; mi++)
#pragma unroll
        for (int ni = 0; ni < 8; ni++)
#pragma unroll
            for (int q = 0; q < 4; q++) acc[mi][ni][q] = 0.f;

    int lrow[4], lcb[4];
    uint32_t lsw[4];
#pragma unroll
    for (int it = 0; it < 4; it++) {
        int u = tid + it * 256;
        lrow[it] = u >> 3;
        lcb[it]  = u & 7;
        lsw[it]  = sw128((uint32_t)(lrow[it] * 128 + lcb[it] * 16));
    }

    const int a_row = wm + (lane & 15);
    const int a_kof = (lane >> 4) * 8;
    const int b_row = wn + ((lane >> 4) << 3) + (lane & 7);
    const int b_kof = ((lane >> 3) & 1) * 8;

    auto issue = [&](int kc, int buf) {
        uint32_t sbuf = sbase + buf * 32768;
#pragma unroll
        for (int it = 0; it < 4; it++) {
            int col = k0 + kc * 64 + lcb[it] * 8;
            cp_async16(sbuf + lsw[it],         A + (size_t)(bm + lrow[it]) * K + col);
            cp_async16(sbuf + 16384 + lsw[it], B + (size_t)(bn + lrow[it]) * K + col);
        }
        cp_commit();
    };

    issue(0, 0);
    for (int g = 0; g < nch; g++) {
        if (g + 1 < nch) {
            issue(g + 1, (g + 1) & 1);
            asm volatile("cp.async.wait_group 1;" ::: "memory");
        } else {
            asm volatile("cp.async.wait_group 0;" ::: "memory");
        }
        __syncthreads();
        uint32_t sbuf = sbase + (g & 1) * 32768;
        const uint32_t sA = sbuf, sB = sbuf + 16384;
#pragma unroll
        for (int kk = 0; kk < 64; kk += 16) {
            uint32_t af[2][4], bf[4][4];
#pragma unroll
            for (int mi = 0; mi < 2; mi++)
                ldsm_x4(af[mi], sA + sw128((uint32_t)((a_row + mi * 16) * 128 + (kk + a_kof) * 2)));
#pragma unroll
            for (int np = 0; np < 4; np++)
                ldsm_x4(bf[np], sB + sw128((uint32_t)((b_row + np * 16) * 128 + (kk + b_kof) * 2)));
#pragma unroll
            for (int mi = 0; mi < 2; mi++)
#pragma unroll
                for (int ni = 0; ni < 8; ni++)
                    mma_bf16(acc[mi][ni], af[mi],
                             bf[ni >> 1][(ni & 1) * 2], bf[ni >> 1][(ni & 1) * 2 + 1]);
        }
        __syncthreads();
    }

    const int er = lane >> 2, ec = (lane & 3) * 2;
    if (gridDim.z == 1) {
#pragma unroll
        for (int mi = 0; mi < 2; mi++) {
            int row0 = bm + wm + mi * 16 + er;
#pragma unroll
            for (int ni = 0; ni < 8; ni++) {
                int col = bn + wn + ni * 8 + ec;
                *reinterpret_cast<float2*>(C + (size_t)row0 * N + col) =
                    make_float2(acc[mi][ni][0], acc[mi][ni][1]);
                *reinterpret_cast<float2*>(C + (size_t)(row0 + 8) * N + col) =
                    make_float2(acc[mi][ni][2], acc[mi][ni][3]);
            }
        }
    } else {
#pragma unroll
        for (int mi = 0; mi < 2; mi++) {
            int row0 = bm + wm + mi * 16 + er;
#pragma unroll
            for (int ni = 0; ni < 8; ni++) {
                int col = bn + wn + ni * 8 + ec;
                atomicAdd(C + (size_t)row0 * N + col,       acc[mi][ni][0]);
                atomicAdd(C + (size_t)row0 * N + col + 1,   acc[mi][ni][1]);
                atomicAdd(C + (size_t)(row0 + 8) * N + col,     acc[mi][ni][2]);
                atomicAdd(C + (size_t)(row0 + 8) * N + col + 1, acc[mi][ni][3]);
            }
        }
    }
}

// ==================== sparse aggregation ====================
__global__ void gcn_agg_kernel(const float* __restrict__ xw, const float* __restrict__ bias,
                               float* __restrict__ out, int F, int do_tanh)
{
    int v = blockIdx.x, f = threadIdx.x;
    __shared__ int   sid[256];
    __shared__ float snw[256];
    int nb = d_cnt_in[v], base = d_off_in[v];
    float dv = d_dis_sp[v];
    float acc = 0.f;
    int CH = blockDim.x;
    for (int c0 = 0; c0 < nb; c0 += CH) {
        int m = min(CH, nb - c0);
        __syncthreads();
        if (f < m) {
            int r = d_csc_src[base + c0 + f];
            sid[f] = r;
            snw[f] = d_dis_sp[r];
        }
        __syncthreads();
#pragma unroll 4
        for (int e = 0; e < m; e++)
            acc += snw[e] * xw[(size_t)sid[e] * F + f];
    }
    float o = dv * acc + dv * dv * xw[(size_t)v * F + f] + bias[f];
    out[(size_t)v * F + f] = do_tanh ? tanhf(o) : o;
}

__global__ void s_agg_kernel(const float* __restrict__ xwp, const float* __restrict__ bp,
                             float* __restrict__ s)
{
    int v = blockIdx.x, t = threadIdx.x;
    __shared__ int   sid[256];
    __shared__ float snw[256];
    int nb = d_cnt_out[v], base = d_off_out[v];
    float dv = d_dis_dn[v];
    float a0 = 0.f, a1 = 0.f, a2 = 0.f, a3 = 0.f;
    for (int c0 = 0; c0 < nb; c0 += 256) {
        int m = min(256, nb - c0);
        __syncthreads();
        if (t < m) {
            int c = d_csr_dst[base + c0 + t];
            sid[t] = c;
            snw[t] = (c == v) ? 0.f : d_dis_dn[c];
        }
        __syncthreads();
#pragma unroll 4
        for (int e = 0; e < m; e++) {
            float w = snw[e];
            const float* xr = xwp + (size_t)sid[e] * KCL;
            a0 += w * xr[t];       a1 += w * xr[t + 256];
            a2 += w * xr[t + 512]; a3 += w * xr[t + 768];
        }
    }
    const float* xv = xwp + (size_t)v * KCL;
    float dvv = dv * dv;
    s[(size_t)v * KCL + t]       = dv * a0 + dvv * xv[t]       + bp[t];
    s[(size_t)v * KCL + t + 256] = dv * a1 + dvv * xv[t + 256] + bp[t + 256];
    s[(size_t)v * KCL + t + 512] = dv * a2 + dvv * xv[t + 512] + bp[t + 512];
    s[(size_t)v * KCL + t + 768] = dv * a3 + dvv * xv[t + 768] + bp[t + 768];
}

__global__ void t_agg_kernel(const float* __restrict__ ss, float* __restrict__ tt)
{
    int v = blockIdx.x, t = threadIdx.x;
    __shared__ int sid[256];
    int nb = d_cnt_out[v], base = d_off_out[v];
    float a0 = 0.f, a1 = 0.f, a2 = 0.f, a3 = 0.f;
    for (int c0 = 0; c0 < nb; c0 += 256) {
        int m = min(256, nb - c0);
        __syncthreads();
        if (t < m) sid[t] = d_csr_dst[base + c0 + t];
        __syncthreads();
#pragma unroll 4
        for (int e = 0; e < m; e++) {
            const float* xr = ss + (size_t)sid[e] * KCL;
            a0 += xr[t];       a1 += xr[t + 256];
            a2 += xr[t + 512]; a3 += xr[t + 768];
        }
    }
    tt[(size_t)v * KCL + t]       = a0;
    tt[(size_t)v * KCL + t + 256] = a1;
    tt[(size_t)v * KCL + t + 512] = a2;
    tt[(size_t)v * KCL + t + 768] = a3;
}

__global__ void softmax_ent_kernel(float* __restrict__ s)
{
    int v = blockIdx.x, t = threadIdx.x;
    float* row = s + (size_t)v * KCL;
    float x0 = row[t], x1 = row[t + 256], x2 = row[t + 512], x3 = row[t + 768];
    __shared__ float red[256];
    float mx = fmaxf(fmaxf(x0, x1), fmaxf(x2, x3));
    red[t] = mx; __syncthreads();
    for (int o = 128; o > 0; o >>= 1) { if (t < o) red[t] = fmaxf(red[t], red[t + o]); __syncthreads(); }
    float m = red[0]; __syncthreads();
    float e0 = expf(x0 - m), e1 = expf(x1 - m), e2 = expf(x2 - m), e3 = expf(x3 - m);
    red[t] = e0 + e1 + e2 + e3; __syncthreads();
    for (int o = 128; o > 0; o >>= 1) { if (t < o) red[t] += red[t + o]; __syncthreads(); }
    float inv = 1.0f / red[0]; __syncthreads();
    float p0 = e0 * inv, p1 = e1 * inv, p2 = e2 * inv, p3 = e3 * inv;
    row[t] = p0; row[t + 256] = p1; row[t + 512] = p2; row[t + 768] = p3;
    float ent = -(p0 * logf(p0 + 1e-15f) + p1 * logf(p1 + 1e-15f) +
                  p2 * logf(p2 + 1e-15f) + p3 * logf(p3 + 1e-15f));
    red[t] = ent; __syncthreads();
    for (int o = 128; o > 0; o >>= 1) { if (t < o) red[t] += red[t + o]; __syncthreads(); }
    if (t == 0) atomicAdd(&d_scal[0], (double)red[0]);
}

// dot product of two big arrays -> d_scal[slot]  (cross = <A S, S> = <t, s>)
__global__ void dot_kernel(const float* __restrict__ a, const float* __restrict__ b,
                           int n, int slot)
{
    int i = (blockIdx.x * blockDim.x + threadIdx.x) * 4;
    float p = 0.f;
    int stride = gridDim.x * blockDim.x * 4;
    for (; i < n; i += stride) {
        float4 va = *reinterpret_cast<const float4*>(a + i);
        float4 vb = *reinterpret_cast<const float4*>(b + i);
        p += va.x * vb.x + va.y * vb.y + va.z * vb.z + va.w * vb.w;
    }
    __shared__ float red[256];
    red[threadIdx.x] = p; __syncthreads();
    for (int o = 128; o > 0; o >>= 1) { if (threadIdx.x < o) red[threadIdx.x] += red[threadIdx.x + o]; __syncthreads(); }
    if (threadIdx.x == 0) atomicAdd(&d_scal[slot], (double)red[0]);
}

__global__ void dupsq_kernel()
{
    int v = blockIdx.x, t = threadIdx.x;
    int nb = d_cnt_out[v], base = d_off_out[v];
    int tot = 0;
    for (int i = t; i < nb; i += blockDim.x) {
        int ci = d_csr_dst[base + i];
        int c = 0;
        for (int j = 0; j < nb; j++) c += (d_csr_dst[base + j] == ci) ? 1 : 0;
        tot += c;
    }
    __shared__ int red[256];
    red[t] = tot; __syncthreads();
    for (int o = 128; o > 0; o >>= 1) { if (t < o) red[t] += red[t + o]; __syncthreads(); }
    if (t == 0 && red[0] != 0) atomicAdd(&d_scal[2], (double)red[0]);
}

__global__ void sq_reduce_kernel(const float* __restrict__ a, int n, int slot)
{
    int i = blockIdx.x * blockDim.x + threadIdx.x;
    float p = 0.f;
    for (; i < n; i += gridDim.x * blockDim.x) { float x = a[i]; p += x * x; }
    __shared__ float red[256];
    red[threadIdx.x] = p; __syncthreads();
    for (int o = 128; o > 0; o >>= 1) { if (threadIdx.x < o) red[threadIdx.x] += red[threadIdx.x + o]; __syncthreads(); }
    if (threadIdx.x == 0) atomicAdd(&d_scal[slot], (double)red[0]);
}

__global__ void finalize_kernel(float* __restrict__ out_link, float* __restrict__ out_ent)
{
    double v = d_scal[2] - 2.0 * d_scal[1] + d_scal[3];
    if (v < 0.0) v = 0.0;
    *out_link = (float)(0.1 * sqrt(v) / ((double)N_NODES * (double)N_NODES));
    *out_ent  = (float)(0.1 * (d_scal[0] / (double)N_NODES));
}

// ==================== host side ====================
static void gemm3(const __nv_bfloat16* Ah, const __nv_bfloat16* Al,
                  const __nv_bfloat16* Bh, const __nv_bfloat16* Bl,
                  float* C, int M, int N, int K, int SK)
{
    static int attr_done = 0;
    if (!attr_done) {
        cudaFuncSetAttribute(gemm3_mma_kernel, cudaFuncAttributeMaxDynamicSharedMemorySize,
                             GEMM3_SMEM_BYTES);
        attr_done = 1;
    }
    if (SK > 1)
        zero_kernel<<<((M * N) / 4 + 255) / 256, 256>>>(C, M * N);
    gemm3_mma_kernel<<<dim3(N / 128, M / 128, SK), 256, GEMM3_SMEM_BYTES>>>(Ah, Al, Bh, Bl, C, M, N, K);
}
static void gemm1(const __nv_bfloat16* A, const __nv_bfloat16* B,
                  float* C, int M, int N, int K, int SK)
{
    static int attr_done = 0;
    if (!attr_done) {
        cudaFuncSetAttribute(gemm1_mma_kernel, cudaFuncAttributeMaxDynamicSharedMemorySize,
                             GEMM1_SMEM_BYTES);
        attr_done = 1;
    }
    if (SK > 1)
        zero_kernel<<<((M * N) / 4 + 255) / 256, 256>>>(C, M * N);
    gemm1_mma_kernel<<<dim3(N / 128, M / 128, SK), 256, GEMM1_SMEM_BYTES>>>(A, B, C, M, N, K);
}
static void split_f(const float* in, __nv_bfloat16* hi, __nv_bfloat16* lo, int n)
{
    split_kernel<<<(n / 4 + 255) / 256, 256>>>(in, hi, lo, n);
}
static void tsplit_f(const float* in, __nv_bfloat16* hi, __nv_bfloat16* lo, int R, int C)
{
    tsplit_kernel<<<dim3(C / 32, R / 32), dim3(32, 8)>>>(in, hi, lo, R, C);
}

extern "C" void kernel_launch(void* const* d_in, const int* in_sizes, int n_in,
                              void* d_out, int out_size)
{
    const float* nodes = (const float*)d_in[0];
    const int*   ei    = (const int*)d_in[1];
    const float* W1 = (const float*)d_in[3];  const float* b1 = (const float*)d_in[4];
    const float* W2 = (const float*)d_in[5];  const float* b2 = (const float*)d_in[6];
    const float* Wp = (const float*)d_in[7];  const float* bp = (const float*)d_in[8];
    const float* W3 = (const float*)d_in[9];  const float* b3 = (const float*)d_in[10];
    const float* W4 = (const float*)d_in[11]; const float* b4 = (const float*)d_in[12];
    const float* W5 = (const float*)d_in[13]; const float* b5 = (const float*)d_in[14];
    int E = in_sizes[1] / 2;

    float* out      = (float*)d_out;
    float* out_x    = out;
    float* out_adj  = out + (size_t)N_NODES * FEAT;
    float* out_link = out + (size_t)N_NODES * FEAT + (size_t)N_NODES * N_NODES;
    float* out_ent  = out_link + 1;

    float *x1, *x2, *xw, *s, *t, *Mb, *xp, *adjp, *G, *xo;
    cudaGetSymbolAddress((void**)&x1,   g_x1);
    cudaGetSymbolAddress((void**)&x2,   g_x2);
    cudaGetSymbolAddress((void**)&xw,   g_xw);
    cudaGetSymbolAddress((void**)&s,    g_s);
    cudaGetSymbolAddress((void**)&t,    g_t);
    cudaGetSymbolAddress((void**)&Mb,   g_M);
    cudaGetSymbolAddress((void**)&xp,   g_xp);
    cudaGetSymbolAddress((void**)&adjp, g_adjp);
    cudaGetSymbolAddress((void**)&G,    g_G);
    cudaGetSymbolAddress((void**)&xo,   g_xo);

    __nv_bfloat16 *nhi,*nlo,*xhi,*xlo,*wthi,*wtlo,*shi,*slo,*sthi,*stlo;
    __nv_bfloat16 *x2thi,*x2tlo,*tthi,*ttlo,*xpthi,*xptlo,*apthi,*aptlo,*mbhi,*mblo;
    cudaGetSymbolAddress((void**)&nhi,  g_nhi);  cudaGetSymbolAddress((void**)&nlo,  g_nlo);
    cudaGetSymbolAddress((void**)&xhi,  g_xhi);  cudaGetSymbolAddress((void**)&xlo,  g_xlo);
    cudaGetSymbolAddress((void**)&wthi, g_wthi); cudaGetSymbolAddress((void**)&wtlo, g_wtlo);
    cudaGetSymbolAddress((void**)&shi,  g_shi);  cudaGetSymbolAddress((void**)&slo,  g_slo);
    cudaGetSymbolAddress((void**)&sthi, g_sthi); cudaGetSymbolAddress((void**)&stlo, g_stlo);
    cudaGetSymbolAddress((void**)&x2thi,g_x2thi);cudaGetSymbolAddress((void**)&x2tlo,g_x2tlo);
    cudaGetSymbolAddress((void**)&tthi, g_tthi); cudaGetSymbolAddress((void**)&ttlo, g_ttlo);
    cudaGetSymbolAddress((void**)&xpthi,g_xpthi);cudaGetSymbolAddress((void**)&xptlo,g_xptlo);
    cudaGetSymbolAddress((void**)&apthi,g_apthi);cudaGetSymbolAddress((void**)&aptlo,g_aptlo);
    cudaGetSymbolAddress((void**)&mbhi, g_mbhi); cudaGetSymbolAddress((void**)&mblo, g_mblo);

    // graph preprocessing
    init_zero_kernel<<<(N_NODES + 255) / 256, 256>>>();
    count_kernel<<<(E + 255) / 256, 256>>>(ei, E);
    scan_kernel<<<1, 1024>>>();
    fill_kernel<<<(E + 255) / 256, 256>>>(ei, E);

    // ---- encoder ----
    split_f(nodes, nhi, nlo, N_NODES * FEAT);
    tsplit_f(W1, wthi, wtlo, FEAT, HID);                     // [HID, FEAT]
    gemm3(nhi, nlo, wthi, wtlo, xw, N_NODES, HID, FEAT, 2);
    gcn_agg_kernel<<<N_NODES, HID>>>(xw, b1, x1, HID, 1);

    split_f(x1, xhi, xlo, N_NODES * HID);
    tsplit_f(W2, wthi, wtlo, HID, HID);
    gemm3(xhi, xlo, wthi, wtlo, xw, N_NODES, HID, HID, 4);
    gcn_agg_kernel<<<N_NODES, HID>>>(xw, b2, x2, HID, 1);

    // ---- assignment ----
    split_f(x2, xhi, xlo, N_NODES * HID);
    tsplit_f(Wp, wthi, wtlo, HID, KCL);                      // [KCL, HID]
    gemm3(xhi, xlo, wthi, wtlo, xw, N_NODES, KCL, HID, 1);
    s_agg_kernel<<<N_NODES, 256>>>(xw, bp, s);
    softmax_ent_kernel<<<N_NODES, 256>>>(s);

    // ---- pooling ----
    split_f(s, shi, slo, N_NODES * KCL);
    tsplit_f(s, sthi, stlo, N_NODES, KCL);                   // S^T [KCL, N]
    tsplit_f(x2, x2thi, x2tlo, N_NODES, HID);                // x2^T [HID, N]
    gemm3(sthi, stlo, x2thi, x2tlo, xp, KCL, HID, N_NODES, 16);   // xp = S^T x2 (signed)
    t_agg_kernel<<<N_NODES, 256>>>(s, t);                    // t = A S  (positive)
    tsplit_f(t, tthi, ttlo, N_NODES, KCL);                   // t^T [KCL, N]
    gemm1(sthi, tthi, adjp, KCL, KCL, N_NODES, 4);           // adjp = S^T A S (positive)
    gemm1(sthi, sthi, G, KCL, KCL, N_NODES, 4);              // G = S^T S (positive)

    // link-loss pieces: cross = <A S, S> = <t, s>
    dot_kernel<<<1024, 256>>>(t, s, N_NODES * KCL, 1);
    dupsq_kernel<<<N_NODES, 256>>>();
    sq_reduce_kernel<<<1024, 256>>>(G, KCL * KCL, 3);

    // ---- un-pool ----
    tsplit_f(xp, xpthi, xptlo, KCL, HID);                    // xp^T [HID, KCL]
    gemm3(shi, slo, xpthi, xptlo, xo, N_NODES, HID, KCL, 4);      // xo = S xp (signed)
    tsplit_f(adjp, apthi, aptlo, KCL, KCL);                  // adjp^T
    gemm1(shi, apthi, Mb, N_NODES, KCL, KCL, 1);             // Mb = S adjp (positive)
    split_f(Mb, mbhi, mblo, N_NODES * KCL);
    gemm1(mbhi, shi, out_adj, N_NODES, N_NODES, KCL, 1);     // adj_out = Mb S^T (positive)

    // ---- decoder ----
    split_f(xo, xhi, xlo, N_NODES * HID);
    tsplit_f(W3, wthi, wtlo, HID, HID);
    gemm3(xhi, xlo, wthi, wtlo, xw, N_NODES, HID, HID, 4);
    gcn_agg_kernel<<<N_NODES, HID>>>(xw, b3, x1, HID, 1);

    split_f(x1, xhi, xlo, N_NODES * HID);
    tsplit_f(W4, wthi, wtlo, HID, HID);
    gemm3(xhi, xlo, wthi, wtlo, xw, N_NODES, HID, HID, 4);
    gcn_agg_kernel<<<N_NODES, HID>>>(xw, b4, x2, HID, 1);

    split_f(x2, xhi, xlo, N_NODES * HID);
    tsplit_f(W5, wthi, wtlo, HID, FEAT);                     // [FEAT, HID]
    gemm3(xhi, xlo, wthi, wtlo, xw, N_NODES, FEAT, HID, 4);
    gcn_agg_kernel<<<N_NODES, FEAT>>>(xw, b5, out_x, FEAT, 0);

    // scalars
    finalize_kernel<<<1, 1>>>(out_link, out_ent);
}

// round 11
// speedup vs baseline: 1.5950x; 1.0374x over previous
#include <cuda_runtime.h>
#include <cuda_bf16.h>
#include <math.h>
#include <stdint.h>

// Problem constants (fixed for this dataset)
#define N_NODES 4096
#define FEAT    128
#define HID     256
#define KCL     1024
#define NE      131072

// ==================== device scratch ====================
__device__ __align__(16) int   d_cnt_in [N_NODES];
__device__ __align__(16) int   d_cnt_out[N_NODES];
__device__ __align__(16) int   d_selfc  [N_NODES];
__device__ __align__(16) int   d_cur_in [N_NODES];
__device__ __align__(16) int   d_cur_out[N_NODES];
__device__ __align__(16) int   d_off_in [N_NODES];
__device__ __align__(16) int   d_off_out[N_NODES];
__device__ __align__(16) int   d_csc_src[NE];
__device__ __align__(16) int   d_csr_dst[NE];
__device__ __align__(16) float d_dis_sp [N_NODES];
__device__ __align__(16) float d_dis_dn [N_NODES];
__device__ double d_scal[4];   // [0]=ent [1]=cross [2]=sum adj^2 [3]=||G||^2

__device__ __align__(16) float g_x1 [N_NODES*HID];
__device__ __align__(16) float g_x2 [N_NODES*HID];
__device__ __align__(16) float g_xw [N_NODES*KCL];
__device__ __align__(16) float g_s  [N_NODES*KCL];
__device__ __align__(16) float g_t  [N_NODES*KCL];
__device__ __align__(16) float g_xp [KCL*HID];
__device__ __align__(16) float g_adjp[KCL*KCL];
__device__ __align__(16) float g_G  [KCL*KCL];
__device__ __align__(16) float g_xo [N_NODES*HID];

// bf16 split operand buffers
__device__ __align__(16) __nv_bfloat16 g_nhi [N_NODES*FEAT],  g_nlo [N_NODES*FEAT];
__device__ __align__(16) __nv_bfloat16 g_xhi [N_NODES*HID],   g_xlo [N_NODES*HID];
__device__ __align__(16) __nv_bfloat16 g_wthi[KCL*HID],       g_wtlo[KCL*HID];
__device__ __align__(16) __nv_bfloat16 g_shi [N_NODES*KCL],   g_slo [N_NODES*KCL];
__device__ __align__(16) __nv_bfloat16 g_sthi[KCL*N_NODES],   g_stlo[KCL*N_NODES];
__device__ __align__(16) __nv_bfloat16 g_tthi[KCL*N_NODES],   g_ttlo[KCL*N_NODES];
__device__ __align__(16) __nv_bfloat16 g_xpthi[HID*KCL],      g_xptlo[HID*KCL];
__device__ __align__(16) __nv_bfloat16 g_apthi[KCL*KCL],      g_aptlo[KCL*KCL];
__device__ __align__(16) __nv_bfloat16 g_mbhi[N_NODES*KCL];

// ==================== setup kernels ====================
__global__ void init_zero_kernel() {
    int i = blockIdx.x * blockDim.x + threadIdx.x;
    if (i < N_NODES) {
        d_cnt_in[i] = 0; d_cnt_out[i] = 0; d_selfc[i] = 0;
        d_cur_in[i] = 0; d_cur_out[i] = 0;
    }
    if (i < 4) d_scal[i] = 0.0;
}

__global__ void zero_kernel(float* __restrict__ p, int n) {
    int i = (blockIdx.x * blockDim.x + threadIdx.x) * 4;
    if (i < n) *reinterpret_cast<float4*>(p + i) = make_float4(0.f, 0.f, 0.f, 0.f);
}

__global__ void count_kernel(const int* __restrict__ ei, int E) {
    int e = blockIdx.x * blockDim.x + threadIdx.x;
    if (e >= E) return;
    int r = ei[e];
    int c = ei[E + e];
    atomicAdd(&d_cnt_out[r], 1);
    atomicAdd(&d_cnt_in[c], 1);
    if (r == c) atomicAdd(&d_selfc[r], 1);
}

__global__ void scan_kernel() {
    __shared__ int sh[1024];
    int t = threadIdx.x;
    {
        int v = t * 4;
        int a0 = d_cnt_in[v], a1 = d_cnt_in[v+1], a2 = d_cnt_in[v+2], a3 = d_cnt_in[v+3];
        int tot = a0 + a1 + a2 + a3;
        sh[t] = tot; __syncthreads();
        for (int o = 1; o < 1024; o <<= 1) {
            int x = (t >= o) ? sh[t - o] : 0;
            __syncthreads();
            sh[t] += x;
            __syncthreads();
        }
        int excl = sh[t] - tot;
        d_off_in[v]   = excl;
        d_off_in[v+1] = excl + a0;
        d_off_in[v+2] = excl + a0 + a1;
        d_off_in[v+3] = excl + a0 + a1 + a2;
        d_dis_sp[v]   = rsqrtf((float)(a0 + 1));
        d_dis_sp[v+1] = rsqrtf((float)(a1 + 1));
        d_dis_sp[v+2] = rsqrtf((float)(a2 + 1));
        d_dis_sp[v+3] = rsqrtf((float)(a3 + 1));
        __syncthreads();
    }
    {
        int v = t * 4;
        int a0 = d_cnt_out[v], a1 = d_cnt_out[v+1], a2 = d_cnt_out[v+2], a3 = d_cnt_out[v+3];
        int tot = a0 + a1 + a2 + a3;
        sh[t] = tot; __syncthreads();
        for (int o = 1; o < 1024; o <<= 1) {
            int x = (t >= o) ? sh[t - o] : 0;
            __syncthreads();
            sh[t] += x;
            __syncthreads();
        }
        int excl = sh[t] - tot;
        d_off_out[v]   = excl;
        d_off_out[v+1] = excl + a0;
        d_off_out[v+2] = excl + a0 + a1;
        d_off_out[v+3] = excl + a0 + a1 + a2;
        d_dis_dn[v]   = rsqrtf((float)(a0 - d_selfc[v]   + 1));
        d_dis_dn[v+1] = rsqrtf((float)(a1 - d_selfc[v+1] + 1));
        d_dis_dn[v+2] = rsqrtf((float)(a2 - d_selfc[v+2] + 1));
        d_dis_dn[v+3] = rsqrtf((float)(a3 - d_selfc[v+3] + 1));
    }
}

__global__ void fill_kernel(const int* __restrict__ ei, int E) {
    int e = blockIdx.x * blockDim.x + threadIdx.x;
    if (e >= E) return;
    int r = ei[e];
    int c = ei[E + e];
    int p = atomicAdd(&d_cur_in[c], 1);
    d_csc_src[d_off_in[c] + p] = r;
    int q = atomicAdd(&d_cur_out[r], 1);
    d_csr_dst[d_off_out[r] + q] = c;
}

// ==================== split / transpose-split ====================
__global__ void split_kernel(const float* __restrict__ in,
                             __nv_bfloat16* __restrict__ hi,
                             __nv_bfloat16* __restrict__ lo, int n)
{
    int i = (blockIdx.x * blockDim.x + threadIdx.x) * 4;
    if (i >= n) return;
    float4 v = *reinterpret_cast<const float4*>(in + i);
    __nv_bfloat16 h0 = __float2bfloat16(v.x);
    __nv_bfloat16 h1 = __float2bfloat16(v.y);
    __nv_bfloat16 h2 = __float2bfloat16(v.z);
    __nv_bfloat16 h3 = __float2bfloat16(v.w);
    __nv_bfloat162 hh0 = {h0, h1}, hh1 = {h2, h3};
    *reinterpret_cast<__nv_bfloat162*>(hi + i)     = hh0;
    *reinterpret_cast<__nv_bfloat162*>(hi + i + 2) = hh1;
    __nv_bfloat162 ll0 = {__float2bfloat16(v.x - __bfloat162float(h0)),
                          __float2bfloat16(v.y - __bfloat162float(h1))};
    __nv_bfloat162 ll1 = {__float2bfloat16(v.z - __bfloat162float(h2)),
                          __float2bfloat16(v.w - __bfloat162float(h3))};
    *reinterpret_cast<__nv_bfloat162*>(lo + i)     = ll0;
    *reinterpret_cast<__nv_bfloat162*>(lo + i + 2) = ll1;
}

// in fp32 [R,C] -> hi/lo bf16 [C,R]
__global__ void tsplit_kernel(const float* __restrict__ in,
                              __nv_bfloat16* __restrict__ hi,
                              __nv_bfloat16* __restrict__ lo, int R, int C)
{
    __shared__ float tile[32][33];
    int c0 = blockIdx.x * 32, r0 = blockIdx.y * 32;
    int tx = threadIdx.x, ty = threadIdx.y;  // 32 x 8
#pragma unroll
    for (int j = 0; j < 32; j += 8)
        tile[ty + j][tx] = in[(size_t)(r0 + ty + j) * C + c0 + tx];
    __syncthreads();
#pragma unroll
    for (int j = 0; j < 32; j += 8) {
        float x = tile[tx][ty + j];
        __nv_bfloat16 h = __float2bfloat16(x);
        size_t o = (size_t)(c0 + ty + j) * R + r0 + tx;
        hi[o] = h;
        lo[o] = __float2bfloat16(x - __bfloat162float(h));
    }
}

// ==================== HMMA common helpers ====================
__device__ __forceinline__ uint32_t smem_u32(const void* p) {
    uint32_t a;
    asm("{ .reg .u64 t; cvta.to.shared.u64 t, %1; cvt.u32.u64 %0, t; }" : "=r"(a) : "l"(p));
    return a;
}
__device__ __forceinline__ void cp_async16(uint32_t saddr, const void* gaddr) {
    asm volatile("cp.async.cg.shared.global [%0], [%1], 16;" :: "r"(saddr), "l"(gaddr));
}
__device__ __forceinline__ void cp_commit() {
    asm volatile("cp.async.commit_group;");
}
__device__ __forceinline__ void ldsm_x4(uint32_t* r, uint32_t addr) {
    asm volatile("ldmatrix.sync.aligned.m8n8.x4.shared.b16 {%0,%1,%2,%3}, [%4];"
        : "=r"(r[0]), "=r"(r[1]), "=r"(r[2]), "=r"(r[3]) : "r"(addr));
}
__device__ __forceinline__ void mma_bf16(float* d, const uint32_t* a, uint32_t b0, uint32_t b1) {
    asm volatile(
        "mma.sync.aligned.m16n8k16.row.col.f32.bf16.bf16.f32 "
        "{%0,%1,%2,%3}, {%4,%5,%6,%7}, {%8,%9}, {%0,%1,%2,%3};"
        : "+f"(d[0]), "+f"(d[1]), "+f"(d[2]), "+f"(d[3])
        : "r"(a[0]), "r"(a[1]), "r"(a[2]), "r"(a[3]), "r"(b0), "r"(b1));
}
__device__ __forceinline__ uint32_t sw128(uint32_t off) {
    return off ^ ((off >> 3) & 0x70);
}

// ==================== 3-term fused split GEMM ====================
// C[M,N] fp32 row-major (+)= Ahi*Bhi^T + Alo*Bhi^T + Ahi*Blo^T (K-major bf16).
// M,N mult of 128; per-z K slice mult of 64.  SMEM: 2 bufs x [Ahi|Alo|Bhi|Blo] x 16KB.
#define GEMM3_SMEM_BYTES 131072

__global__ __launch_bounds__(256) void gemm3_mma_kernel(
    const __nv_bfloat16* __restrict__ Ahi, const __nv_bfloat16* __restrict__ Alo,
    const __nv_bfloat16* __restrict__ Bhi, const __nv_bfloat16* __restrict__ Blo,
    float* __restrict__ C, int M, int N, int K)
{
    extern __shared__ char smem[];
    const uint32_t sbase = smem_u32(smem);
    const int tid = threadIdx.x, lane = tid & 31, wid = tid >> 5;
    const int bm = blockIdx.y * 128, bn = blockIdx.x * 128;
    const int wm = (wid >> 1) * 32;
    const int wn = (wid & 1) * 64;

    const int ksz = K / gridDim.z;
    const int k0  = blockIdx.z * ksz;
    const int nch = ksz >> 6;

    float acc[2][8][4];
#pragma unroll
    for (int mi = 0; mi < 2; mi++)
#pragma unroll
        for (int ni = 0; ni < 8; ni++)
#pragma unroll
            for (int q = 0; q < 4; q++) acc[mi][ni][q] = 0.f;

    int lrow[4], lcb[4];
    uint32_t lsw[4];
#pragma unroll
    for (int it = 0; it < 4; it++) {
        int u = tid + it * 256;
        lrow[it] = u >> 3;
        lcb[it]  = u & 7;
        lsw[it]  = sw128((uint32_t)(lrow[it] * 128 + lcb[it] * 16));
    }

    const int a_row = wm + (lane & 15);
    const int a_kof = (lane >> 4) * 8;
    const int b_row = wn + ((lane >> 4) << 3) + (lane & 7);
    const int b_kof = ((lane >> 3) & 1) * 8;

    auto issue = [&](int kc, int buf) {
        uint32_t sbuf = sbase + buf * 65536;
        const __nv_bfloat16* tp[4] = { Ahi, Alo, Bhi, Blo };
#pragma unroll
        for (int tI = 0; tI < 4; tI++) {
            int ro = (tI < 2) ? bm : bn;
            const __nv_bfloat16* P = tp[tI];
            uint32_t sdst = sbuf + tI * 16384;
#pragma unroll
            for (int it = 0; it < 4; it++)
                cp_async16(sdst + lsw[it],
                           P + (size_t)(ro + lrow[it]) * K + k0 + kc * 64 + lcb[it] * 8);
        }
        cp_commit();
    };

    issue(0, 0);
    for (int g = 0; g < nch; g++) {
        if (g + 1 < nch) {
            issue(g + 1, (g + 1) & 1);
            asm volatile("cp.async.wait_group 1;" ::: "memory");
        } else {
            asm volatile("cp.async.wait_group 0;" ::: "memory");
        }
        __syncthreads();
        uint32_t sbuf = sbase + (g & 1) * 65536;
        const uint32_t sAh = sbuf, sAl = sbuf + 16384, sBh = sbuf + 32768, sBl = sbuf + 49152;
#pragma unroll
        for (int kk = 0; kk < 64; kk += 16) {
            uint32_t ah[2][4], al[2][4], bh[4][4], bl[4][4];
#pragma unroll
            for (int mi = 0; mi < 2; mi++) {
                uint32_t off = sw128((uint32_t)((a_row + mi * 16) * 128 + (kk + a_kof) * 2));
                ldsm_x4(ah[mi], sAh + off);
                ldsm_x4(al[mi], sAl + off);
            }
#pragma unroll
            for (int np = 0; np < 4; np++) {
                uint32_t off = sw128((uint32_t)((b_row + np * 16) * 128 + (kk + b_kof) * 2));
                ldsm_x4(bh[np], sBh + off);
                ldsm_x4(bl[np], sBl + off);
            }
#pragma unroll
            for (int mi = 0; mi < 2; mi++)
#pragma unroll
                for (int ni = 0; ni < 8; ni++) {
                    uint32_t b0h = bh[ni >> 1][(ni & 1) * 2], b1h = bh[ni >> 1][(ni & 1) * 2 + 1];
                    uint32_t b0l = bl[ni >> 1][(ni & 1) * 2], b1l = bl[ni >> 1][(ni & 1) * 2 + 1];
                    mma_bf16(acc[mi][ni], ah[mi], b0h, b1h);
                    mma_bf16(acc[mi][ni], al[mi], b0h, b1h);
                    mma_bf16(acc[mi][ni], ah[mi], b0l, b1l);
                }
        }
        __syncthreads();
    }

    const int er = lane >> 2, ec = (lane & 3) * 2;
    if (gridDim.z == 1) {
#pragma unroll
        for (int mi = 0; mi < 2; mi++) {
            int row0 = bm + wm + mi * 16 + er;
#pragma unroll
            for (int ni = 0; ni < 8; ni++) {
                int col = bn + wn + ni * 8 + ec;
                *reinterpret_cast<float2*>(C + (size_t)row0 * N + col) =
                    make_float2(acc[mi][ni][0], acc[mi][ni][1]);
                *reinterpret_cast<float2*>(C + (size_t)(row0 + 8) * N + col) =
                    make_float2(acc[mi][ni][2], acc[mi][ni][3]);
            }
        }
    } else {
#pragma unroll
        for (int mi = 0; mi < 2; mi++) {
            int row0 = bm + wm + mi * 16 + er;
#pragma unroll
            for (int ni = 0; ni < 8; ni++) {
                int col = bn + wn + ni * 8 + ec;
                atomicAdd(C + (size_t)row0 * N + col,       acc[mi][ni][0]);
                atomicAdd(C + (size_t)row0 * N + col + 1,   acc[mi][ni][1]);
                atomicAdd(C + (size_t)(row0 + 8) * N + col,     acc[mi][ni][2]);
                atomicAdd(C + (size_t)(row0 + 8) * N + col + 1, acc[mi][ni][3]);
            }
        }
    }
}

// ==================== 1-term plain bf16 GEMM (positive chains) ====================
// OUT_BF16=0: C fp32 (split-K via atomics allowed). OUT_BF16=1: C bf16, SK must be 1.
#define GEMM1_SMEM_BYTES 65536

template <int OUT_BF16>
__global__ __launch_bounds__(256) void gemm1_mma_kernel(
    const __nv_bfloat16* __restrict__ A, const __nv_bfloat16* __restrict__ B,
    void* __restrict__ Cv, int M, int N, int K)
{
    extern __shared__ char smem[];
    const uint32_t sbase = smem_u32(smem);
    const int tid = threadIdx.x, lane = tid & 31, wid = tid >> 5;
    const int bm = blockIdx.y * 128, bn = blockIdx.x * 128;
    const int wm = (wid >> 1) * 32;
    const int wn = (wid & 1) * 64;

    const int ksz = K / gridDim.z;
    const int k0  = blockIdx.z * ksz;
    const int nch = ksz >> 6;

    float acc[2][8][4];
#pragma unroll
    for (int mi = 0; mi < 2; mi++)
#pragma unroll
        for (int ni = 0; ni < 8; ni++)
#pragma unroll
            for (int q = 0; q < 4; q++) acc[mi][ni][q] = 0.f;

    int lrow[4], lcb[4];
    uint32_t lsw[4];
#pragma unroll
    for (int it = 0; it < 4; it++) {
        int u = tid + it * 256;
        lrow[it] = u >> 3;
        lcb[it]  = u & 7;
        lsw[it]  = sw128((uint32_t)(lrow[it] * 128 + lcb[it] * 16));
    }

    const int a_row = wm + (lane & 15);
    const int a_kof = (lane >> 4) * 8;
    const int b_row = wn + ((lane >> 4) << 3) + (lane & 7);
    const int b_kof = ((lane >> 3) & 1) * 8;

    auto issue = [&](int kc, int buf) {
        uint32_t sbuf = sbase + buf * 32768;
#pragma unroll
        for (int it = 0; it < 4; it++) {
            int col = k0 + kc * 64 + lcb[it] * 8;
            cp_async16(sbuf + lsw[it],         A + (size_t)(bm + lrow[it]) * K + col);
            cp_async16(sbuf + 16384 + lsw[it], B + (size_t)(bn + lrow[it]) * K + col);
        }
        cp_commit();
    };

    issue(0, 0);
    for (int g = 0; g < nch; g++) {
        if (g + 1 < nch) {
            issue(g + 1, (g + 1) & 1);
            asm volatile("cp.async.wait_group 1;" ::: "memory");
        } else {
            asm volatile("cp.async.wait_group 0;" ::: "memory");
        }
        __syncthreads();
        uint32_t sbuf = sbase + (g & 1) * 32768;
        const uint32_t sA = sbuf, sB = sbuf + 16384;
#pragma unroll
        for (int kk = 0; kk < 64; kk += 16) {
            uint32_t af[2][4], bf[4][4];
#pragma unroll
            for (int mi = 0; mi < 2; mi++)
                ldsm_x4(af[mi], sA + sw128((uint32_t)((a_row + mi * 16) * 128 + (kk + a_kof) * 2)));
#pragma unroll
            for (int np = 0; np < 4; np++)
                ldsm_x4(bf[np], sB + sw128((uint32_t)((b_row + np * 16) * 128 + (kk + b_kof) * 2)));
#pragma unroll
            for (int mi = 0; mi < 2; mi++)
#pragma unroll
                for (int ni = 0; ni < 8; ni++)
                    mma_bf16(acc[mi][ni], af[mi],
                             bf[ni >> 1][(ni & 1) * 2], bf[ni >> 1][(ni & 1) * 2 + 1]);
        }
        __syncthreads();
    }

    const int er = lane >> 2, ec = (lane & 3) * 2;
    if (OUT_BF16) {
        __nv_bfloat16* C = (__nv_bfloat16*)Cv;
#pragma unroll
        for (int mi = 0; mi < 2; mi++) {
            int row0 = bm + wm + mi * 16 + er;
#pragma unroll
            for (int ni = 0; ni < 8; ni++) {
                int col = bn + wn + ni * 8 + ec;
                __nv_bfloat162 p0 = {__float2bfloat16(acc[mi][ni][0]),
                                     __float2bfloat16(acc[mi][ni][1])};
                __nv_bfloat162 p1 = {__float2bfloat16(acc[mi][ni][2]),
                                     __float2bfloat16(acc[mi][ni][3])};
                *reinterpret_cast<__nv_bfloat162*>(C + (size_t)row0 * N + col)       = p0;
                *reinterpret_cast<__nv_bfloat162*>(C + (size_t)(row0 + 8) * N + col) = p1;
            }
        }
    } else {
        float* C = (float*)Cv;
        if (gridDim.z == 1) {
#pragma unroll
            for (int mi = 0; mi < 2; mi++) {
                int row0 = bm + wm + mi * 16 + er;
#pragma unroll
                for (int ni = 0; ni < 8; ni++) {
                    int col = bn + wn + ni * 8 + ec;
                    *reinterpret_cast<float2*>(C + (size_t)row0 * N + col) =
                        make_float2(acc[mi][ni][0], acc[mi][ni][1]);
                    *reinterpret_cast<float2*>(C + (size_t)(row0 + 8) * N + col) =
                        make_float2(acc[mi][ni][2], acc[mi][ni][3]);
                }
            }
        } else {
#pragma unroll
            for (int mi = 0; mi < 2; mi++) {
                int row0 = bm + wm + mi * 16 + er;
#pragma unroll
                for (int ni = 0; ni < 8; ni++) {
                    int col = bn + wn + ni * 8 + ec;
                    atomicAdd(C + (size_t)row0 * N + col,       acc[mi][ni][0]);
                    atomicAdd(C + (size_t)row0 * N + col + 1,   acc[mi][ni][1]);
                    atomicAdd(C + (size_t)(row0 + 8) * N + col,     acc[mi][ni][2]);
                    atomicAdd(C + (size_t)(row0 + 8) * N + col + 1, acc[mi][ni][3]);
                }
            }
        }
    }
}

// ==================== sparse aggregation ====================
__global__ void gcn_agg_kernel(const float* __restrict__ xw, const float* __restrict__ bias,
                               float* __restrict__ out, int F, int do_tanh)
{
    int v = blockIdx.x, f = threadIdx.x;
    __shared__ int   sid[256];
    __shared__ float snw[256];
    int nb = d_cnt_in[v], base = d_off_in[v];
    float dv = d_dis_sp[v];
    float acc = 0.f;
    int CH = blockDim.x;
    for (int c0 = 0; c0 < nb; c0 += CH) {
        int m = min(CH, nb - c0);
        __syncthreads();
        if (f < m) {
            int r = d_csc_src[base + c0 + f];
            sid[f] = r;
            snw[f] = d_dis_sp[r];
        }
        __syncthreads();
#pragma unroll 4
        for (int e = 0; e < m; e++)
            acc += snw[e] * xw[(size_t)sid[e] * F + f];
    }
    float o = dv * acc + dv * dv * xw[(size_t)v * F + f] + bias[f];
    out[(size_t)v * F + f] = do_tanh ? tanhf(o) : o;
}

// y[v,:] = dis_dn[v]*sum_{(v->c), c!=v} dis_dn[c]*x2[c,:] + dis_dn[v]^2*x2[v,:]   (F=HID=256)
__global__ void y_agg_kernel(const float* __restrict__ x2, float* __restrict__ y)
{
    int v = blockIdx.x, f = threadIdx.x;  // 256 threads, 1 col each
    __shared__ int   sid[256];
    __shared__ float snw[256];
    int nb = d_cnt_out[v], base = d_off_out[v];
    float dv = d_dis_dn[v];
    float acc = 0.f;
    for (int c0 = 0; c0 < nb; c0 += 256) {
        int m = min(256, nb - c0);
        __syncthreads();
        if (f < m) {
            int c = d_csr_dst[base + c0 + f];
            sid[f] = c;
            snw[f] = (c == v) ? 0.f : d_dis_dn[c];
        }
        __syncthreads();
#pragma unroll 4
        for (int e = 0; e < m; e++)
            acc += snw[e] * x2[(size_t)sid[e] * HID + f];
    }
    y[(size_t)v * HID + f] = dv * acc + dv * dv * x2[(size_t)v * HID + f];
}

__global__ void t_agg_kernel(const float* __restrict__ ss, float* __restrict__ tt)
{
    int v = blockIdx.x, t = threadIdx.x;
    __shared__ int sid[256];
    int nb = d_cnt_out[v], base = d_off_out[v];
    float a0 = 0.f, a1 = 0.f, a2 = 0.f, a3 = 0.f;
    for (int c0 = 0; c0 < nb; c0 += 256) {
        int m = min(256, nb - c0);
        __syncthreads();
        if (t < m) sid[t] = d_csr_dst[base + c0 + t];
        __syncthreads();
#pragma unroll 4
        for (int e = 0; e < m; e++) {
            const float* xr = ss + (size_t)sid[e] * KCL;
            a0 += xr[t];       a1 += xr[t + 256];
            a2 += xr[t + 512]; a3 += xr[t + 768];
        }
    }
    tt[(size_t)v * KCL + t]       = a0;
    tt[(size_t)v * KCL + t + 256] = a1;
    tt[(size_t)v * KCL + t + 512] = a2;
    tt[(size_t)v * KCL + t + 768] = a3;
}

// in-place: s = softmax(s + bp) over each row; accumulate entropy
__global__ void softmax_ent_kernel(float* __restrict__ s, const float* __restrict__ bp)
{
    int v = blockIdx.x, t = threadIdx.x;
    float* row = s + (size_t)v * KCL;
    float x0 = row[t]       + bp[t];
    float x1 = row[t + 256] + bp[t + 256];
    float x2 = row[t + 512] + bp[t + 512];
    float x3 = row[t + 768] + bp[t + 768];
    __shared__ float red[256];
    float mx = fmaxf(fmaxf(x0, x1), fmaxf(x2, x3));
    red[t] = mx; __syncthreads();
    for (int o = 128; o > 0; o >>= 1) { if (t < o) red[t] = fmaxf(red[t], red[t + o]); __syncthreads(); }
    float m = red[0]; __syncthreads();
    float e0 = expf(x0 - m), e1 = expf(x1 - m), e2 = expf(x2 - m), e3 = expf(x3 - m);
    red[t] = e0 + e1 + e2 + e3; __syncthreads();
    for (int o = 128; o > 0; o >>= 1) { if (t < o) red[t] += red[t + o]; __syncthreads(); }
    float inv = 1.0f / red[0]; __syncthreads();
    float p0 = e0 * inv, p1 = e1 * inv, p2 = e2 * inv, p3 = e3 * inv;
    row[t] = p0; row[t + 256] = p1; row[t + 512] = p2; row[t + 768] = p3;
    float ent = -(p0 * logf(p0 + 1e-15f) + p1 * logf(p1 + 1e-15f) +
                  p2 * logf(p2 + 1e-15f) + p3 * logf(p3 + 1e-15f));
    red[t] = ent; __syncthreads();
    for (int o = 128; o > 0; o >>= 1) { if (t < o) red[t] += red[t + o]; __syncthreads(); }
    if (t == 0) atomicAdd(&d_scal[0], (double)red[0]);
}

// dot product of two big arrays -> d_scal[slot]  (cross = <A S, S> = <t, s>)
__global__ void dot_kernel(const float* __restrict__ a, const float* __restrict__ b,
                           int n, int slot)
{
    int i = (blockIdx.x * blockDim.x + threadIdx.x) * 4;
    float p = 0.f;
    int stride = gridDim.x * blockDim.x * 4;
    for (; i < n; i += stride) {
        float4 va = *reinterpret_cast<const float4*>(a + i);
        float4 vb = *reinterpret_cast<const float4*>(b + i);
        p += va.x * vb.x + va.y * vb.y + va.z * vb.z + va.w * vb.w;
    }
    __shared__ float red[256];
    red[threadIdx.x] = p; __syncthreads();
    for (int o = 128; o > 0; o >>= 1) { if (threadIdx.x < o) red[threadIdx.x] += red[threadIdx.x + o]; __syncthreads(); }
    if (threadIdx.x == 0) atomicAdd(&d_scal[slot], (double)red[0]);
}

__global__ void dupsq_kernel()
{
    int v = blockIdx.x, t = threadIdx.x;
    int nb = d_cnt_out[v], base = d_off_out[v];
    int tot = 0;
    for (int i = t; i < nb; i += blockDim.x) {
        int ci = d_csr_dst[base + i];
        int c = 0;
        for (int j = 0; j < nb; j++) c += (d_csr_dst[base + j] == ci) ? 1 : 0;
        tot += c;
    }
    __shared__ int red[256];
    red[t] = tot; __syncthreads();
    for (int o = 128; o > 0; o >>= 1) { if (t < o) red[t] += red[t + o]; __syncthreads(); }
    if (t == 0 && red[0] != 0) atomicAdd(&d_scal[2], (double)red[0]);
}

__global__ void sq_reduce_kernel(const float* __restrict__ a, int n, int slot)
{
    int i = blockIdx.x * blockDim.x + threadIdx.x;
    float p = 0.f;
    for (; i < n; i += gridDim.x * blockDim.x) { float x = a[i]; p += x * x; }
    __shared__ float red[256];
    red[threadIdx.x] = p; __syncthreads();
    for (int o = 128; o > 0; o >>= 1) { if (threadIdx.x < o) red[threadIdx.x] += red[threadIdx.x + o]; __syncthreads(); }
    if (threadIdx.x == 0) atomicAdd(&d_scal[slot], (double)red[0]);
}

__global__ void finalize_kernel(float* __restrict__ out_link, float* __restrict__ out_ent)
{
    double v = d_scal[2] - 2.0 * d_scal[1] + d_scal[3];
    if (v < 0.0) v = 0.0;
    *out_link = (float)(0.1 * sqrt(v) / ((double)N_NODES * (double)N_NODES));
    *out_ent  = (float)(0.1 * (d_scal[0] / (double)N_NODES));
}

// ==================== host side ====================
static void gemm3(const __nv_bfloat16* Ah, const __nv_bfloat16* Al,
                  const __nv_bfloat16* Bh, const __nv_bfloat16* Bl,
                  float* C, int M, int N, int K, int SK)
{
    static int attr_done = 0;
    if (!attr_done) {
        cudaFuncSetAttribute(gemm3_mma_kernel, cudaFuncAttributeMaxDynamicSharedMemorySize,
                             GEMM3_SMEM_BYTES);
        attr_done = 1;
    }
    if (SK > 1)
        zero_kernel<<<((M * N) / 4 + 255) / 256, 256>>>(C, M * N);
    gemm3_mma_kernel<<<dim3(N / 128, M / 128, SK), 256, GEMM3_SMEM_BYTES>>>(Ah, Al, Bh, Bl, C, M, N, K);
}
static void gemm1(const __nv_bfloat16* A, const __nv_bfloat16* B,
                  float* C, int M, int N, int K, int SK)
{
    static int attr_done = 0;
    if (!attr_done) {
        cudaFuncSetAttribute(gemm1_mma_kernel<0>, cudaFuncAttributeMaxDynamicSharedMemorySize,
                             GEMM1_SMEM_BYTES);
        attr_done = 1;
    }
    if (SK > 1)
        zero_kernel<<<((M * N) / 4 + 255) / 256, 256>>>(C, M * N);
    gemm1_mma_kernel<0><<<dim3(N / 128, M / 128, SK), 256, GEMM1_SMEM_BYTES>>>(A, B, C, M, N, K);
}
static void gemm1_bf16(const __nv_bfloat16* A, const __nv_bfloat16* B,
                       __nv_bfloat16* C, int M, int N, int K)
{
    static int attr_done = 0;
    if (!attr_done) {
        cudaFuncSetAttribute(gemm1_mma_kernel<1>, cudaFuncAttributeMaxDynamicSharedMemorySize,
                             GEMM1_SMEM_BYTES);
        attr_done = 1;
    }
    gemm1_mma_kernel<1><<<dim3(N / 128, M / 128, 1), 256, GEMM1_SMEM_BYTES>>>(A, B, C, M, N, K);
}
static void split_f(const float* in, __nv_bfloat16* hi, __nv_bfloat16* lo, int n)
{
    split_kernel<<<(n / 4 + 255) / 256, 256>>>(in, hi, lo, n);
}
static void tsplit_f(const float* in, __nv_bfloat16* hi, __nv_bfloat16* lo, int R, int C)
{
    tsplit_kernel<<<dim3(C / 32, R / 32), dim3(32, 8)>>>(in, hi, lo, R, C);
}

extern "C" void kernel_launch(void* const* d_in, const int* in_sizes, int n_in,
                              void* d_out, int out_size)
{
    const float* nodes = (const float*)d_in[0];
    const int*   ei    = (const int*)d_in[1];
    const float* W1 = (const float*)d_in[3];  const float* b1 = (const float*)d_in[4];
    const float* W2 = (const float*)d_in[5];  const float* b2 = (const float*)d_in[6];
    const float* Wp = (const float*)d_in[7];  const float* bp = (const float*)d_in[8];
    const float* W3 = (const float*)d_in[9];  const float* b3 = (const float*)d_in[10];
    const float* W4 = (const float*)d_in[11]; const float* b4 = (const float*)d_in[12];
    const float* W5 = (const float*)d_in[13]; const float* b5 = (const float*)d_in[14];
    int E = in_sizes[1] / 2;

    float* out      = (float*)d_out;
    float* out_x    = out;
    float* out_adj  = out + (size_t)N_NODES * FEAT;
    float* out_link = out + (size_t)N_NODES * FEAT + (size_t)N_NODES * N_NODES;
    float* out_ent  = out_link + 1;

    float *x1, *x2, *xw, *s, *t, *xp, *adjp, *G, *xo;
    cudaGetSymbolAddress((void**)&x1,   g_x1);
    cudaGetSymbolAddress((void**)&x2,   g_x2);
    cudaGetSymbolAddress((void**)&xw,   g_xw);
    cudaGetSymbolAddress((void**)&s,    g_s);
    cudaGetSymbolAddress((void**)&t,    g_t);
    cudaGetSymbolAddress((void**)&xp,   g_xp);
    cudaGetSymbolAddress((void**)&adjp, g_adjp);
    cudaGetSymbolAddress((void**)&G,    g_G);
    cudaGetSymbolAddress((void**)&xo,   g_xo);

    __nv_bfloat16 *nhi,*nlo,*xhi,*xlo,*wthi,*wtlo,*shi,*slo,*sthi,*stlo;
    __nv_bfloat16 *tthi,*ttlo,*xpthi,*xptlo,*apthi,*aptlo,*mbhi;
    cudaGetSymbolAddress((void**)&nhi,  g_nhi);  cudaGetSymbolAddress((void**)&nlo,  g_nlo);
    cudaGetSymbolAddress((void**)&xhi,  g_xhi);  cudaGetSymbolAddress((void**)&xlo,  g_xlo);
    cudaGetSymbolAddress((void**)&wthi, g_wthi); cudaGetSymbolAddress((void**)&wtlo, g_wtlo);
    cudaGetSymbolAddress((void**)&shi,  g_shi);  cudaGetSymbolAddress((void**)&slo,  g_slo);
    cudaGetSymbolAddress((void**)&sthi, g_sthi); cudaGetSymbolAddress((void**)&stlo, g_stlo);
    cudaGetSymbolAddress((void**)&tthi, g_tthi); cudaGetSymbolAddress((void**)&ttlo, g_ttlo);
    cudaGetSymbolAddress((void**)&xpthi,g_xpthi);cudaGetSymbolAddress((void**)&xptlo,g_xptlo);
    cudaGetSymbolAddress((void**)&apthi,g_apthi);cudaGetSymbolAddress((void**)&aptlo,g_aptlo);
    cudaGetSymbolAddress((void**)&mbhi, g_mbhi);

    // graph preprocessing
    init_zero_kernel<<<(N_NODES + 255) / 256, 256>>>();
    count_kernel<<<(E + 255) / 256, 256>>>(ei, E);
    scan_kernel<<<1, 1024>>>();
    fill_kernel<<<(E + 255) / 256, 256>>>(ei, E);

    // ---- encoder ----
    split_f(nodes, nhi, nlo, N_NODES * FEAT);
    tsplit_f(W1, wthi, wtlo, FEAT, HID);                     // [HID, FEAT]
    gemm3(nhi, nlo, wthi, wtlo, xw, N_NODES, HID, FEAT, 2);
    gcn_agg_kernel<<<N_NODES, HID>>>(xw, b1, x1, HID, 1);

    split_f(x1, xhi, xlo, N_NODES * HID);
    tsplit_f(W2, wthi, wtlo, HID, HID);
    gemm3(xhi, xlo, wthi, wtlo, xw, N_NODES, HID, HID, 4);
    gcn_agg_kernel<<<N_NODES, HID>>>(xw, b2, x2, HID, 1);

    // ---- assignment: s = (A_dn @ x2) @ Wp + bp ; softmax ----
    y_agg_kernel<<<N_NODES, HID>>>(x2, x1);                  // y (reuse x1) = A_dn x2
    split_f(x1, xhi, xlo, N_NODES * HID);
    tsplit_f(Wp, wthi, wtlo, HID, KCL);                      // [KCL, HID]
    gemm3(xhi, xlo, wthi, wtlo, s, N_NODES, KCL, HID, 1);    // s = y Wp
    softmax_ent_kernel<<<N_NODES, 256>>>(s, bp);             // s = softmax(s + bp)

    // ---- pooling ----
    split_f(s, shi, slo, N_NODES * KCL);
    tsplit_f(s, sthi, stlo, N_NODES, KCL);                   // S^T [KCL, N]
    tsplit_f(x2, xhi, xlo, N_NODES, HID);                    // x2^T [HID, N] (reuse xhi/xlo... careful: size HID*N = N*HID, fits)
    gemm3(sthi, stlo, xhi, xlo, xp, KCL, HID, N_NODES, 16);  // xp = S^T x2 (signed)
    t_agg_kernel<<<N_NODES, 256>>>(s, t);                    // t = A S  (positive)
    tsplit_f(t, tthi, ttlo, N_NODES, KCL);                   // t^T [KCL, N]
    gemm1(sthi, tthi, adjp, KCL, KCL, N_NODES, 4);           // adjp = S^T A S (positive)
    gemm1(sthi, sthi, G, KCL, KCL, N_NODES, 4);              // G = S^T S (positive)

    // link-loss pieces: cross = <A S, S> = <t, s>
    dot_kernel<<<1024, 256>>>(t, s, N_NODES * KCL, 1);
    dupsq_kernel<<<N_NODES, 256>>>();
    sq_reduce_kernel<<<1024, 256>>>(G, KCL * KCL, 3);

    // ---- un-pool ----
    tsplit_f(xp, xpthi, xptlo, KCL, HID);                    // xp^T [HID, KCL]
    gemm3(shi, slo, xpthi, xptlo, xo, N_NODES, HID, KCL, 4); // xo = S xp (signed)
    tsplit_f(adjp, apthi, aptlo, KCL, KCL);                  // adjp^T
    gemm1_bf16(shi, apthi, mbhi, N_NODES, KCL, KCL);         // Mb = S adjp (positive, bf16 out)
    gemm1(mbhi, shi, out_adj, N_NODES, N_NODES, KCL, 1);     // adj_out = Mb S^T (positive)

    // ---- decoder ----
    split_f(xo, xhi, xlo, N_NODES * HID);
    tsplit_f(W3, wthi, wtlo, HID, HID);
    gemm3(xhi, xlo, wthi, wtlo, xw, N_NODES, HID, HID, 4);
    gcn_agg_kernel<<<N_NODES, HID>>>(xw, b3, x1, HID, 1);

    split_f(x1, xhi, xlo, N_NODES * HID);
    tsplit_f(W4, wthi, wtlo, HID, HID);
    gemm3(xhi, xlo, wthi, wtlo, xw, N_NODES, HID, HID, 4);
    gcn_agg_kernel<<<N_NODES, HID>>>(xw, b4, x2, HID, 1);

    split_f(x2, xhi, xlo, N_NODES * HID);
    tsplit_f(W5, wthi, wtlo, HID, FEAT);                     // [FEAT, HID]
    gemm3(xhi, xlo, wthi, wtlo, xw, N_NODES, FEAT, HID, 4);
    gcn_agg_kernel<<<N_NODES, FEAT>>>(xw, b5, out_x, FEAT, 0);

    // scalars
    finalize_kernel<<<1, 1>>>(out_link, out_ent);
}

// round 12
// speedup vs baseline: 1.6124x; 1.0109x over previous
#include <cuda_runtime.h>
#include <cuda_bf16.h>
#include <math.h>
#include <stdint.h>

// Problem constants (fixed for this dataset)
#define N_NODES 4096
#define FEAT    128
#define HID     256
#define KCL     1024
#define NE      131072

// ==================== device scratch ====================
__device__ __align__(16) int   d_cnt_in [N_NODES];
__device__ __align__(16) int   d_cnt_out[N_NODES];
__device__ __align__(16) int   d_selfc  [N_NODES];
__device__ __align__(16) int   d_cur_in [N_NODES];
__device__ __align__(16) int   d_cur_out[N_NODES];
__device__ __align__(16) int   d_off_in [N_NODES];
__device__ __align__(16) int   d_off_out[N_NODES];
__device__ __align__(16) int   d_csc_src[NE];
__device__ __align__(16) int   d_csr_dst[NE];
__device__ __align__(16) float d_dis_sp [N_NODES];
__device__ __align__(16) float d_dis_dn [N_NODES];
__device__ double d_scal[4];   // [0]=ent [1]=cross [2]=sum adj^2 [3]=||G||^2

__device__ __align__(16) float g_x1 [N_NODES*HID];
__device__ __align__(16) float g_x2 [N_NODES*HID];
__device__ __align__(16) float g_xw [N_NODES*KCL];
__device__ __align__(16) float g_s  [N_NODES*KCL];
__device__ __align__(16) float g_t  [N_NODES*KCL];
__device__ __align__(16) float g_xp [KCL*HID];
__device__ __align__(16) float g_adjp[KCL*KCL];
__device__ __align__(16) float g_G  [KCL*KCL];
__device__ __align__(16) float g_xo [N_NODES*HID];

// bf16 split operand buffers
__device__ __align__(16) __nv_bfloat16 g_nhi [N_NODES*FEAT],  g_nlo [N_NODES*FEAT];
__device__ __align__(16) __nv_bfloat16 g_xhi [N_NODES*HID],   g_xlo [N_NODES*HID];
__device__ __align__(16) __nv_bfloat16 g_wthi[KCL*HID],       g_wtlo[KCL*HID];
__device__ __align__(16) __nv_bfloat16 g_shi [N_NODES*KCL],   g_slo [N_NODES*KCL];
__device__ __align__(16) __nv_bfloat16 g_sthi[KCL*N_NODES],   g_stlo[KCL*N_NODES];
__device__ __align__(16) __nv_bfloat16 g_tthi[KCL*N_NODES],   g_ttlo[KCL*N_NODES];
__device__ __align__(16) __nv_bfloat16 g_xpthi[HID*KCL],      g_xptlo[HID*KCL];
__device__ __align__(16) __nv_bfloat16 g_apthi[KCL*KCL],      g_aptlo[KCL*KCL];
__device__ __align__(16) __nv_bfloat16 g_mbhi[N_NODES*KCL];

// ==================== setup kernels ====================
__global__ void init_zero_kernel() {
    int i = blockIdx.x * blockDim.x + threadIdx.x;
    if (i < N_NODES) {
        d_cnt_in[i] = 0; d_cnt_out[i] = 0; d_selfc[i] = 0;
        d_cur_in[i] = 0; d_cur_out[i] = 0;
    }
    if (i < 4) d_scal[i] = 0.0;
}

__global__ void zero_kernel(float* __restrict__ p, int n) {
    int i = (blockIdx.x * blockDim.x + threadIdx.x) * 4;
    if (i < n) *reinterpret_cast<float4*>(p + i) = make_float4(0.f, 0.f, 0.f, 0.f);
}

__global__ void count_kernel(const int* __restrict__ ei, int E) {
    int e = blockIdx.x * blockDim.x + threadIdx.x;
    if (e >= E) return;
    int r = ei[e];
    int c = ei[E + e];
    atomicAdd(&d_cnt_out[r], 1);
    atomicAdd(&d_cnt_in[c], 1);
    if (r == c) atomicAdd(&d_selfc[r], 1);
}

__global__ void scan_kernel() {
    __shared__ int sh[1024];
    int t = threadIdx.x;
    {
        int v = t * 4;
        int a0 = d_cnt_in[v], a1 = d_cnt_in[v+1], a2 = d_cnt_in[v+2], a3 = d_cnt_in[v+3];
        int tot = a0 + a1 + a2 + a3;
        sh[t] = tot; __syncthreads();
        for (int o = 1; o < 1024; o <<= 1) {
            int x = (t >= o) ? sh[t - o] : 0;
            __syncthreads();
            sh[t] += x;
            __syncthreads();
        }
        int excl = sh[t] - tot;
        d_off_in[v]   = excl;
        d_off_in[v+1] = excl + a0;
        d_off_in[v+2] = excl + a0 + a1;
        d_off_in[v+3] = excl + a0 + a1 + a2;
        d_dis_sp[v]   = rsqrtf((float)(a0 + 1));
        d_dis_sp[v+1] = rsqrtf((float)(a1 + 1));
        d_dis_sp[v+2] = rsqrtf((float)(a2 + 1));
        d_dis_sp[v+3] = rsqrtf((float)(a3 + 1));
        __syncthreads();
    }
    {
        int v = t * 4;
        int a0 = d_cnt_out[v], a1 = d_cnt_out[v+1], a2 = d_cnt_out[v+2], a3 = d_cnt_out[v+3];
        int tot = a0 + a1 + a2 + a3;
        sh[t] = tot; __syncthreads();
        for (int o = 1; o < 1024; o <<= 1) {
            int x = (t >= o) ? sh[t - o] : 0;
            __syncthreads();
            sh[t] += x;
            __syncthreads();
        }
        int excl = sh[t] - tot;
        d_off_out[v]   = excl;
        d_off_out[v+1] = excl + a0;
        d_off_out[v+2] = excl + a0 + a1;
        d_off_out[v+3] = excl + a0 + a1 + a2;
        d_dis_dn[v]   = rsqrtf((float)(a0 - d_selfc[v]   + 1));
        d_dis_dn[v+1] = rsqrtf((float)(a1 - d_selfc[v+1] + 1));
        d_dis_dn[v+2] = rsqrtf((float)(a2 - d_selfc[v+2] + 1));
        d_dis_dn[v+3] = rsqrtf((float)(a3 - d_selfc[v+3] + 1));
    }
}

__global__ void fill_kernel(const int* __restrict__ ei, int E) {
    int e = blockIdx.x * blockDim.x + threadIdx.x;
    if (e >= E) return;
    int r = ei[e];
    int c = ei[E + e];
    int p = atomicAdd(&d_cur_in[c], 1);
    d_csc_src[d_off_in[c] + p] = r;
    int q = atomicAdd(&d_cur_out[r], 1);
    d_csr_dst[d_off_out[r] + q] = c;
}

// ==================== split / transpose-split ====================
__global__ void split_kernel(const float* __restrict__ in,
                             __nv_bfloat16* __restrict__ hi,
                             __nv_bfloat16* __restrict__ lo, int n)
{
    int i = (blockIdx.x * blockDim.x + threadIdx.x) * 4;
    if (i >= n) return;
    float4 v = *reinterpret_cast<const float4*>(in + i);
    __nv_bfloat16 h0 = __float2bfloat16(v.x);
    __nv_bfloat16 h1 = __float2bfloat16(v.y);
    __nv_bfloat16 h2 = __float2bfloat16(v.z);
    __nv_bfloat16 h3 = __float2bfloat16(v.w);
    __nv_bfloat162 hh0 = {h0, h1}, hh1 = {h2, h3};
    *reinterpret_cast<__nv_bfloat162*>(hi + i)     = hh0;
    *reinterpret_cast<__nv_bfloat162*>(hi + i + 2) = hh1;
    __nv_bfloat162 ll0 = {__float2bfloat16(v.x - __bfloat162float(h0)),
                          __float2bfloat16(v.y - __bfloat162float(h1))};
    __nv_bfloat162 ll1 = {__float2bfloat16(v.z - __bfloat162float(h2)),
                          __float2bfloat16(v.w - __bfloat162float(h3))};
    *reinterpret_cast<__nv_bfloat162*>(lo + i)     = ll0;
    *reinterpret_cast<__nv_bfloat162*>(lo + i + 2) = ll1;
}

// in fp32 [R,C] -> hi/lo bf16 [C,R]
__global__ void tsplit_kernel(const float* __restrict__ in,
                              __nv_bfloat16* __restrict__ hi,
                              __nv_bfloat16* __restrict__ lo, int R, int C)
{
    __shared__ float tile[32][33];
    int c0 = blockIdx.x * 32, r0 = blockIdx.y * 32;
    int tx = threadIdx.x, ty = threadIdx.y;  // 32 x 8
#pragma unroll
    for (int j = 0; j < 32; j += 8)
        tile[ty + j][tx] = in[(size_t)(r0 + ty + j) * C + c0 + tx];
    __syncthreads();
#pragma unroll
    for (int j = 0; j < 32; j += 8) {
        float x = tile[tx][ty + j];
        __nv_bfloat16 h = __float2bfloat16(x);
        size_t o = (size_t)(c0 + ty + j) * R + r0 + tx;
        hi[o] = h;
        lo[o] = __float2bfloat16(x - __bfloat162float(h));
    }
}

// ==================== HMMA common helpers ====================
__device__ __forceinline__ uint32_t smem_u32(const void* p) {
    uint32_t a;
    asm("{ .reg .u64 t; cvta.to.shared.u64 t, %1; cvt.u32.u64 %0, t; }" : "=r"(a) : "l"(p));
    return a;
}
__device__ __forceinline__ void cp_async16(uint32_t saddr, const void* gaddr) {
    asm volatile("cp.async.cg.shared.global [%0], [%1], 16;" :: "r"(saddr), "l"(gaddr));
}
__device__ __forceinline__ void cp_commit() {
    asm volatile("cp.async.commit_group;");
}
__device__ __forceinline__ void ldsm_x4(uint32_t* r, uint32_t addr) {
    asm volatile("ldmatrix.sync.aligned.m8n8.x4.shared.b16 {%0,%1,%2,%3}, [%4];"
        : "=r"(r[0]), "=r"(r[1]), "=r"(r[2]), "=r"(r[3]) : "r"(addr));
}
__device__ __forceinline__ void mma_bf16(float* d, const uint32_t* a, uint32_t b0, uint32_t b1) {
    asm volatile(
        "mma.sync.aligned.m16n8k16.row.col.f32.bf16.bf16.f32 "
        "{%0,%1,%2,%3}, {%4,%5,%6,%7}, {%8,%9}, {%0,%1,%2,%3};"
        : "+f"(d[0]), "+f"(d[1]), "+f"(d[2]), "+f"(d[3])
        : "r"(a[0]), "r"(a[1]), "r"(a[2]), "r"(a[3]), "r"(b0), "r"(b1));
}
__device__ __forceinline__ uint32_t sw128(uint32_t off) {
    return off ^ ((off >> 3) & 0x70);
}

// ==================== 3-term fused split GEMM ====================
// C[M,N] fp32 row-major (+)= Ahi*Bhi^T + Alo*Bhi^T + Ahi*Blo^T (K-major bf16).
// M,N mult of 128; per-z K slice mult of 64.  SMEM: 2 bufs x [Ahi|Alo|Bhi|Blo] x 16KB.
#define GEMM3_SMEM_BYTES 131072

__global__ __launch_bounds__(256) void gemm3_mma_kernel(
    const __nv_bfloat16* __restrict__ Ahi, const __nv_bfloat16* __restrict__ Alo,
    const __nv_bfloat16* __restrict__ Bhi, const __nv_bfloat16* __restrict__ Blo,
    float* __restrict__ C, int M, int N, int K)
{
    extern __shared__ char smem[];
    const uint32_t sbase = smem_u32(smem);
    const int tid = threadIdx.x, lane = tid & 31, wid = tid >> 5;
    const int bm = blockIdx.y * 128, bn = blockIdx.x * 128;
    const int wm = (wid >> 1) * 32;
    const int wn = (wid & 1) * 64;

    const int ksz = K / gridDim.z;
    const int k0  = blockIdx.z * ksz;
    const int nch = ksz >> 6;

    float acc[2][8][4];
#pragma unroll
    for (int mi = 0; mi < 2; mi++)
#pragma unroll
        for (int ni = 0; ni < 8; ni++)
#pragma unroll
            for (int q = 0; q < 4; q++) acc[mi][ni][q] = 0.f;

    int lrow[4], lcb[4];
    uint32_t lsw[4];
#pragma unroll
    for (int it = 0; it < 4; it++) {
        int u = tid + it * 256;
        lrow[it] = u >> 3;
        lcb[it]  = u & 7;
        lsw[it]  = sw128((uint32_t)(lrow[it] * 128 + lcb[it] * 16));
    }

    const int a_row = wm + (lane & 15);
    const int a_kof = (lane >> 4) * 8;
    const int b_row = wn + ((lane >> 4) << 3) + (lane & 7);
    const int b_kof = ((lane >> 3) & 1) * 8;

    auto issue = [&](int kc, int buf) {
        uint32_t sbuf = sbase + buf * 65536;
        const __nv_bfloat16* tp[4] = { Ahi, Alo, Bhi, Blo };
#pragma unroll
        for (int tI = 0; tI < 4; tI++) {
            int ro = (tI < 2) ? bm : bn;
            const __nv_bfloat16* P = tp[tI];
            uint32_t sdst = sbuf + tI * 16384;
#pragma unroll
            for (int it = 0; it < 4; it++)
                cp_async16(sdst + lsw[it],
                           P + (size_t)(ro + lrow[it]) * K + k0 + kc * 64 + lcb[it] * 8);
        }
        cp_commit();
    };

    issue(0, 0);
    for (int g = 0; g < nch; g++) {
        if (g + 1 < nch) {
            issue(g + 1, (g + 1) & 1);
            asm volatile("cp.async.wait_group 1;" ::: "memory");
        } else {
            asm volatile("cp.async.wait_group 0;" ::: "memory");
        }
        __syncthreads();
        uint32_t sbuf = sbase + (g & 1) * 65536;
        const uint32_t sAh = sbuf, sAl = sbuf + 16384, sBh = sbuf + 32768, sBl = sbuf + 49152;
#pragma unroll
        for (int kk = 0; kk < 64; kk += 16) {
            uint32_t ah[2][4], al[2][4], bh[4][4], bl[4][4];
#pragma unroll
            for (int mi = 0; mi < 2; mi++) {
                uint32_t off = sw128((uint32_t)((a_row + mi * 16) * 128 + (kk + a_kof) * 2));
                ldsm_x4(ah[mi], sAh + off);
                ldsm_x4(al[mi], sAl + off);
            }
#pragma unroll
            for (int np = 0; np < 4; np++) {
                uint32_t off = sw128((uint32_t)((b_row + np * 16) * 128 + (kk + b_kof) * 2));
                ldsm_x4(bh[np], sBh + off);
                ldsm_x4(bl[np], sBl + off);
            }
#pragma unroll
            for (int mi = 0; mi < 2; mi++)
#pragma unroll
                for (int ni = 0; ni < 8; ni++) {
                    uint32_t b0h = bh[ni >> 1][(ni & 1) * 2], b1h = bh[ni >> 1][(ni & 1) * 2 + 1];
                    uint32_t b0l = bl[ni >> 1][(ni & 1) * 2], b1l = bl[ni >> 1][(ni & 1) * 2 + 1];
                    mma_bf16(acc[mi][ni], ah[mi], b0h, b1h);
                    mma_bf16(acc[mi][ni], al[mi], b0h, b1h);
                    mma_bf16(acc[mi][ni], ah[mi], b0l, b1l);
                }
        }
        __syncthreads();
    }

    const int er = lane >> 2, ec = (lane & 3) * 2;
    if (gridDim.z == 1) {
#pragma unroll
        for (int mi = 0; mi < 2; mi++) {
            int row0 = bm + wm + mi * 16 + er;
#pragma unroll
            for (int ni = 0; ni < 8; ni++) {
                int col = bn + wn + ni * 8 + ec;
                *reinterpret_cast<float2*>(C + (size_t)row0 * N + col) =
                    make_float2(acc[mi][ni][0], acc[mi][ni][1]);
                *reinterpret_cast<float2*>(C + (size_t)(row0 + 8) * N + col) =
                    make_float2(acc[mi][ni][2], acc[mi][ni][3]);
            }
        }
    } else {
#pragma unroll
        for (int mi = 0; mi < 2; mi++) {
            int row0 = bm + wm + mi * 16 + er;
#pragma unroll
            for (int ni = 0; ni < 8; ni++) {
                int col = bn + wn + ni * 8 + ec;
                atomicAdd(C + (size_t)row0 * N + col,       acc[mi][ni][0]);
                atomicAdd(C + (size_t)row0 * N + col + 1,   acc[mi][ni][1]);
                atomicAdd(C + (size_t)(row0 + 8) * N + col,     acc[mi][ni][2]);
                atomicAdd(C + (size_t)(row0 + 8) * N + col + 1, acc[mi][ni][3]);
            }
        }
    }
}

// ==================== 1-term plain bf16 GEMM (positive chains) ====================
// OUT_BF16=0: C fp32 (split-K via atomics allowed). OUT_BF16=1: C bf16, SK must be 1.
#define GEMM1_SMEM_BYTES 65536

template <int OUT_BF16>
__global__ __launch_bounds__(256) void gemm1_mma_kernel(
    const __nv_bfloat16* __restrict__ A, const __nv_bfloat16* __restrict__ B,
    void* __restrict__ Cv, int M, int N, int K)
{
    extern __shared__ char smem[];
    const uint32_t sbase = smem_u32(smem);
    const int tid = threadIdx.x, lane = tid & 31, wid = tid >> 5;
    const int bm = blockIdx.y * 128, bn = blockIdx.x * 128;
    const int wm = (wid >> 1) * 32;
    const int wn = (wid & 1) * 64;

    const int ksz = K / gridDim.z;
    const int k0  = blockIdx.z * ksz;
    const int nch = ksz >> 6;

    float acc[2][8][4];
#pragma unroll
    for (int mi = 0; mi < 2; mi++)
#pragma unroll
        for (int ni = 0; ni < 8; ni++)
#pragma unroll
            for (int q = 0; q < 4; q++) acc[mi][ni][q] = 0.f;

    int lrow[4], lcb[4];
    uint32_t lsw[4];
#pragma unroll
    for (int it = 0; it < 4; it++) {
        int u = tid + it * 256;
        lrow[it] = u >> 3;
        lcb[it]  = u & 7;
        lsw[it]  = sw128((uint32_t)(lrow[it] * 128 + lcb[it] * 16));
    }

    const int a_row = wm + (lane & 15);
    const int a_kof = (lane >> 4) * 8;
    const int b_row = wn + ((lane >> 4) << 3) + (lane & 7);
    const int b_kof = ((lane >> 3) & 1) * 8;

    auto issue = [&](int kc, int buf) {
        uint32_t sbuf = sbase + buf * 32768;
#pragma unroll
        for (int it = 0; it < 4; it++) {
            int col = k0 + kc * 64 + lcb[it] * 8;
            cp_async16(sbuf + lsw[it],         A + (size_t)(bm + lrow[it]) * K + col);
            cp_async16(sbuf + 16384 + lsw[it], B + (size_t)(bn + lrow[it]) * K + col);
        }
        cp_commit();
    };

    issue(0, 0);
    for (int g = 0; g < nch; g++) {
        if (g + 1 < nch) {
            issue(g + 1, (g + 1) & 1);
            asm volatile("cp.async.wait_group 1;" ::: "memory");
        } else {
            asm volatile("cp.async.wait_group 0;" ::: "memory");
        }
        __syncthreads();
        uint32_t sbuf = sbase + (g & 1) * 32768;
        const uint32_t sA = sbuf, sB = sbuf + 16384;
#pragma unroll
        for (int kk = 0; kk < 64; kk += 16) {
            uint32_t af[2][4], bf[4][4];
#pragma unroll
            for (int mi = 0; mi < 2; mi++)
                ldsm_x4(af[mi], sA + sw128((uint32_t)((a_row + mi * 16) * 128 + (kk + a_kof) * 2)));
#pragma unroll
            for (int np = 0; np < 4; np++)
                ldsm_x4(bf[np], sB + sw128((uint32_t)((b_row + np * 16) * 128 + (kk + b_kof) * 2)));
#pragma unroll
            for (int mi = 0; mi < 2; mi++)
#pragma unroll
                for (int ni = 0; ni < 8; ni++)
                    mma_bf16(acc[mi][ni], af[mi],
                             bf[ni >> 1][(ni & 1) * 2], bf[ni >> 1][(ni & 1) * 2 + 1]);
        }
        __syncthreads();
    }

    const int er = lane >> 2, ec = (lane & 3) * 2;
    if (OUT_BF16) {
        __nv_bfloat16* C = (__nv_bfloat16*)Cv;
#pragma unroll
        for (int mi = 0; mi < 2; mi++) {
            int row0 = bm + wm + mi * 16 + er;
#pragma unroll
            for (int ni = 0; ni < 8; ni++) {
                int col = bn + wn + ni * 8 + ec;
                __nv_bfloat162 p0 = {__float2bfloat16(acc[mi][ni][0]),
                                     __float2bfloat16(acc[mi][ni][1])};
                __nv_bfloat162 p1 = {__float2bfloat16(acc[mi][ni][2]),
                                     __float2bfloat16(acc[mi][ni][3])};
                *reinterpret_cast<__nv_bfloat162*>(C + (size_t)row0 * N + col)       = p0;
                *reinterpret_cast<__nv_bfloat162*>(C + (size_t)(row0 + 8) * N + col) = p1;
            }
        }
    } else {
        float* C = (float*)Cv;
        if (gridDim.z == 1) {
#pragma unroll
            for (int mi = 0; mi < 2; mi++) {
                int row0 = bm + wm + mi * 16 + er;
#pragma unroll
                for (int ni = 0; ni < 8; ni++) {
                    int col = bn + wn + ni * 8 + ec;
                    *reinterpret_cast<float2*>(C + (size_t)row0 * N + col) =
                        make_float2(acc[mi][ni][0], acc[mi][ni][1]);
                    *reinterpret_cast<float2*>(C + (size_t)(row0 + 8) * N + col) =
                        make_float2(acc[mi][ni][2], acc[mi][ni][3]);
                }
            }
        } else {
#pragma unroll
            for (int mi = 0; mi < 2; mi++) {
                int row0 = bm + wm + mi * 16 + er;
#pragma unroll
                for (int ni = 0; ni < 8; ni++) {
                    int col = bn + wn + ni * 8 + ec;
                    atomicAdd(C + (size_t)row0 * N + col,       acc[mi][ni][0]);
                    atomicAdd(C + (size_t)row0 * N + col + 1,   acc[mi][ni][1]);
                    atomicAdd(C + (size_t)(row0 + 8) * N + col,     acc[mi][ni][2]);
                    atomicAdd(C + (size_t)(row0 + 8) * N + col + 1, acc[mi][ni][3]);
                }
            }
        }
    }
}

// ==================== sparse aggregation ====================
__global__ void gcn_agg_kernel(const float* __restrict__ xw, const float* __restrict__ bias,
                               float* __restrict__ out, int F, int do_tanh)
{
    int v = blockIdx.x, f = threadIdx.x;
    __shared__ int   sid[256];
    __shared__ float snw[256];
    int nb = d_cnt_in[v], base = d_off_in[v];
    float dv = d_dis_sp[v];
    float acc = 0.f;
    int CH = blockDim.x;
    for (int c0 = 0; c0 < nb; c0 += CH) {
        int m = min(CH, nb - c0);
        __syncthreads();
        if (f < m) {
            int r = d_csc_src[base + c0 + f];
            sid[f] = r;
            snw[f] = d_dis_sp[r];
        }
        __syncthreads();
#pragma unroll 4
        for (int e = 0; e < m; e++)
            acc += snw[e] * xw[(size_t)sid[e] * F + f];
    }
    float o = dv * acc + dv * dv * xw[(size_t)v * F + f] + bias[f];
    out[(size_t)v * F + f] = do_tanh ? tanhf(o) : o;
}

// y[v,:] = dis_dn[v]*sum_{(v->c), c!=v} dis_dn[c]*x2[c,:] + dis_dn[v]^2*x2[v,:]   (F=HID=256)
__global__ void y_agg_kernel(const float* __restrict__ x2, float* __restrict__ y)
{
    int v = blockIdx.x, f = threadIdx.x;  // 256 threads, 1 col each
    __shared__ int   sid[256];
    __shared__ float snw[256];
    int nb = d_cnt_out[v], base = d_off_out[v];
    float dv = d_dis_dn[v];
    float acc = 0.f;
    for (int c0 = 0; c0 < nb; c0 += 256) {
        int m = min(256, nb - c0);
        __syncthreads();
        if (f < m) {
            int c = d_csr_dst[base + c0 + f];
            sid[f] = c;
            snw[f] = (c == v) ? 0.f : d_dis_dn[c];
        }
        __syncthreads();
#pragma unroll 4
        for (int e = 0; e < m; e++)
            acc += snw[e] * x2[(size_t)sid[e] * HID + f];
    }
    y[(size_t)v * HID + f] = dv * acc + dv * dv * x2[(size_t)v * HID + f];
}

// t[v,:] = sum over CSR edges of bf16(s)[c,:]  (gathers bf16 hi version of s)
__global__ void t_agg_kernel(const __nv_bfloat16* __restrict__ sh, float* __restrict__ tt)
{
    int v = blockIdx.x, t = threadIdx.x;
    __shared__ int sid[256];
    int nb = d_cnt_out[v], base = d_off_out[v];
    float a0 = 0.f, a1 = 0.f, a2 = 0.f, a3 = 0.f;
    for (int c0 = 0; c0 < nb; c0 += 256) {
        int m = min(256, nb - c0);
        __syncthreads();
        if (t < m) sid[t] = d_csr_dst[base + c0 + t];
        __syncthreads();
#pragma unroll 4
        for (int e = 0; e < m; e++) {
            const __nv_bfloat16* xr = sh + (size_t)sid[e] * KCL;
            __nv_bfloat162 p0 = *reinterpret_cast<const __nv_bfloat162*>(xr + t * 2);
            // layout note: we gather pairs (2 cols per thread x 2 groups) to keep
            // 4 cols/thread as before but with 32-bit loads.
            a0 += __bfloat162float(p0.x);
            a1 += __bfloat162float(p0.y);
            __nv_bfloat162 p1 = *reinterpret_cast<const __nv_bfloat162*>(xr + 512 + t * 2);
            a2 += __bfloat162float(p1.x);
            a3 += __bfloat162float(p1.y);
        }
    }
    tt[(size_t)v * KCL + t * 2]       = a0;
    tt[(size_t)v * KCL + t * 2 + 1]   = a1;
    tt[(size_t)v * KCL + 512 + t * 2]     = a2;
    tt[(size_t)v * KCL + 512 + t * 2 + 1] = a3;
}

// in-place: s = softmax(s + bp); writes fp32 s, bf16 hi/lo; accumulates entropy
__global__ void softmax_ent_kernel(float* __restrict__ s, const float* __restrict__ bp,
                                   __nv_bfloat16* __restrict__ shi,
                                   __nv_bfloat16* __restrict__ slo)
{
    int v = blockIdx.x, t = threadIdx.x;
    float* row = s + (size_t)v * KCL;
    float x0 = row[t]       + bp[t];
    float x1 = row[t + 256] + bp[t + 256];
    float x2 = row[t + 512] + bp[t + 512];
    float x3 = row[t + 768] + bp[t + 768];
    __shared__ float red[256];
    float mx = fmaxf(fmaxf(x0, x1), fmaxf(x2, x3));
    red[t] = mx; __syncthreads();
    for (int o = 128; o > 0; o >>= 1) { if (t < o) red[t] = fmaxf(red[t], red[t + o]); __syncthreads(); }
    float m = red[0]; __syncthreads();
    float e0 = expf(x0 - m), e1 = expf(x1 - m), e2 = expf(x2 - m), e3 = expf(x3 - m);
    red[t] = e0 + e1 + e2 + e3; __syncthreads();
    for (int o = 128; o > 0; o >>= 1) { if (t < o) red[t] += red[t + o]; __syncthreads(); }
    float inv = 1.0f / red[0]; __syncthreads();
    float p0 = e0 * inv, p1 = e1 * inv, p2 = e2 * inv, p3 = e3 * inv;
    row[t] = p0; row[t + 256] = p1; row[t + 512] = p2; row[t + 768] = p3;
    __nv_bfloat16* hrow = shi + (size_t)v * KCL;
    __nv_bfloat16* lrow = slo + (size_t)v * KCL;
    float p[4] = {p0, p1, p2, p3};
#pragma unroll
    for (int q = 0; q < 4; q++) {
        __nv_bfloat16 h = __float2bfloat16(p[q]);
        hrow[t + q * 256] = h;
        lrow[t + q * 256] = __float2bfloat16(p[q] - __bfloat162float(h));
    }
    float ent = -(p0 * logf(p0 + 1e-15f) + p1 * logf(p1 + 1e-15f) +
                  p2 * logf(p2 + 1e-15f) + p3 * logf(p3 + 1e-15f));
    red[t] = ent; __syncthreads();
    for (int o = 128; o > 0; o >>= 1) { if (t < o) red[t] += red[t + o]; __syncthreads(); }
    if (t == 0) atomicAdd(&d_scal[0], (double)red[0]);
}

// dot product of two big arrays -> d_scal[slot]  (cross = <A S, S> = <t, s>)
__global__ void dot_kernel(const float* __restrict__ a, const float* __restrict__ b,
                           int n, int slot)
{
    int i = (blockIdx.x * blockDim.x + threadIdx.x) * 4;
    float p = 0.f;
    int stride = gridDim.x * blockDim.x * 4;
    for (; i < n; i += stride) {
        float4 va = *reinterpret_cast<const float4*>(a + i);
        float4 vb = *reinterpret_cast<const float4*>(b + i);
        p += va.x * vb.x + va.y * vb.y + va.z * vb.z + va.w * vb.w;
    }
    __shared__ float red[256];
    red[threadIdx.x] = p; __syncthreads();
    for (int o = 128; o > 0; o >>= 1) { if (threadIdx.x < o) red[threadIdx.x] += red[threadIdx.x + o]; __syncthreads(); }
    if (threadIdx.x == 0) atomicAdd(&d_scal[slot], (double)red[0]);
}

__global__ void dupsq_kernel()
{
    int v = blockIdx.x, t = threadIdx.x;
    int nb = d_cnt_out[v], base = d_off_out[v];
    int tot = 0;
    for (int i = t; i < nb; i += blockDim.x) {
        int ci = d_csr_dst[base + i];
        int c = 0;
        for (int j = 0; j < nb; j++) c += (d_csr_dst[base + j] == ci) ? 1 : 0;
        tot += c;
    }
    __shared__ int red[256];
    red[t] = tot; __syncthreads();
    for (int o = 128; o > 0; o >>= 1) { if (t < o) red[t] += red[t + o]; __syncthreads(); }
    if (t == 0 && red[0] != 0) atomicAdd(&d_scal[2], (double)red[0]);
}

__global__ void sq_reduce_kernel(const float* __restrict__ a, int n, int slot)
{
    int i = blockIdx.x * blockDim.x + threadIdx.x;
    float p = 0.f;
    for (; i < n; i += gridDim.x * blockDim.x) { float x = a[i]; p += x * x; }
    __shared__ float red[256];
    red[threadIdx.x] = p; __syncthreads();
    for (int o = 128; o > 0; o >>= 1) { if (threadIdx.x < o) red[threadIdx.x] += red[threadIdx.x + o]; __syncthreads(); }
    if (threadIdx.x == 0) atomicAdd(&d_scal[slot], (double)red[0]);
}

__global__ void finalize_kernel(float* __restrict__ out_link, float* __restrict__ out_ent)
{
    double v = d_scal[2] - 2.0 * d_scal[1] + d_scal[3];
    if (v < 0.0) v = 0.0;
    *out_link = (float)(0.1 * sqrt(v) / ((double)N_NODES * (double)N_NODES));
    *out_ent  = (float)(0.1 * (d_scal[0] / (double)N_NODES));
}

// ==================== host side ====================
static void gemm3(const __nv_bfloat16* Ah, const __nv_bfloat16* Al,
                  const __nv_bfloat16* Bh, const __nv_bfloat16* Bl,
                  float* C, int M, int N, int K, int SK)
{
    static int attr_done = 0;
    if (!attr_done) {
        cudaFuncSetAttribute(gemm3_mma_kernel, cudaFuncAttributeMaxDynamicSharedMemorySize,
                             GEMM3_SMEM_BYTES);
        attr_done = 1;
    }
    if (SK > 1)
        zero_kernel<<<((M * N) / 4 + 255) / 256, 256>>>(C, M * N);
    gemm3_mma_kernel<<<dim3(N / 128, M / 128, SK), 256, GEMM3_SMEM_BYTES>>>(Ah, Al, Bh, Bl, C, M, N, K);
}
static void gemm1(const __nv_bfloat16* A, const __nv_bfloat16* B,
                  float* C, int M, int N, int K, int SK)
{
    static int attr_done = 0;
    if (!attr_done) {
        cudaFuncSetAttribute(gemm1_mma_kernel<0>, cudaFuncAttributeMaxDynamicSharedMemorySize,
                             GEMM1_SMEM_BYTES);
        attr_done = 1;
    }
    if (SK > 1)
        zero_kernel<<<((M * N) / 4 + 255) / 256, 256>>>(C, M * N);
    gemm1_mma_kernel<0><<<dim3(N / 128, M / 128, SK), 256, GEMM1_SMEM_BYTES>>>(A, B, C, M, N, K);
}
static void gemm1_bf16(const __nv_bfloat16* A, const __nv_bfloat16* B,
                       __nv_bfloat16* C, int M, int N, int K)
{
    static int attr_done = 0;
    if (!attr_done) {
        cudaFuncSetAttribute(gemm1_mma_kernel<1>, cudaFuncAttributeMaxDynamicSharedMemorySize,
                             GEMM1_SMEM_BYTES);
        attr_done = 1;
    }
    gemm1_mma_kernel<1><<<dim3(N / 128, M / 128, 1), 256, GEMM1_SMEM_BYTES>>>(A, B, C, M, N, K);
}
static void split_f(const float* in, __nv_bfloat16* hi, __nv_bfloat16* lo, int n)
{
    split_kernel<<<(n / 4 + 255) / 256, 256>>>(in, hi, lo, n);
}
static void tsplit_f(const float* in, __nv_bfloat16* hi, __nv_bfloat16* lo, int R, int C)
{
    tsplit_kernel<<<dim3(C / 32, R / 32), dim3(32, 8)>>>(in, hi, lo, R, C);
}

extern "C" void kernel_launch(void* const* d_in, const int* in_sizes, int n_in,
                              void* d_out, int out_size)
{
    const float* nodes = (const float*)d_in[0];
    const int*   ei    = (const int*)d_in[1];
    const float* W1 = (const float*)d_in[3];  const float* b1 = (const float*)d_in[4];
    const float* W2 = (const float*)d_in[5];  const float* b2 = (const float*)d_in[6];
    const float* Wp = (const float*)d_in[7];  const float* bp = (const float*)d_in[8];
    const float* W3 = (const float*)d_in[9];  const float* b3 = (const float*)d_in[10];
    const float* W4 = (const float*)d_in[11]; const float* b4 = (const float*)d_in[12];
    const float* W5 = (const float*)d_in[13]; const float* b5 = (const float*)d_in[14];
    int E = in_sizes[1] / 2;

    float* out      = (float*)d_out;
    float* out_x    = out;
    float* out_adj  = out + (size_t)N_NODES * FEAT;
    float* out_link = out + (size_t)N_NODES * FEAT + (size_t)N_NODES * N_NODES;
    float* out_ent  = out_link + 1;

    float *x1, *x2, *xw, *s, *t, *xp, *adjp, *G, *xo;
    cudaGetSymbolAddress((void**)&x1,   g_x1);
    cudaGetSymbolAddress((void**)&x2,   g_x2);
    cudaGetSymbolAddress((void**)&xw,   g_xw);
    cudaGetSymbolAddress((void**)&s,    g_s);
    cudaGetSymbolAddress((void**)&t,    g_t);
    cudaGetSymbolAddress((void**)&xp,   g_xp);
    cudaGetSymbolAddress((void**)&adjp, g_adjp);
    cudaGetSymbolAddress((void**)&G,    g_G);
    cudaGetSymbolAddress((void**)&xo,   g_xo);

    __nv_bfloat16 *nhi,*nlo,*xhi,*xlo,*wthi,*wtlo,*shi,*slo,*sthi,*stlo;
    __nv_bfloat16 *tthi,*ttlo,*xpthi,*xptlo,*apthi,*aptlo,*mbhi;
    cudaGetSymbolAddress((void**)&nhi,  g_nhi);  cudaGetSymbolAddress((void**)&nlo,  g_nlo);
    cudaGetSymbolAddress((void**)&xhi,  g_xhi);  cudaGetSymbolAddress((void**)&xlo,  g_xlo);
    cudaGetSymbolAddress((void**)&wthi, g_wthi); cudaGetSymbolAddress((void**)&wtlo, g_wtlo);
    cudaGetSymbolAddress((void**)&shi,  g_shi);  cudaGetSymbolAddress((void**)&slo,  g_slo);
    cudaGetSymbolAddress((void**)&sthi, g_sthi); cudaGetSymbolAddress((void**)&stlo, g_stlo);
    cudaGetSymbolAddress((void**)&tthi, g_tthi); cudaGetSymbolAddress((void**)&ttlo, g_ttlo);
    cudaGetSymbolAddress((void**)&xpthi,g_xpthi);cudaGetSymbolAddress((void**)&xptlo,g_xptlo);
    cudaGetSymbolAddress((void**)&apthi,g_apthi);cudaGetSymbolAddress((void**)&aptlo,g_aptlo);
    cudaGetSymbolAddress((void**)&mbhi, g_mbhi);

    // graph preprocessing
    init_zero_kernel<<<(N_NODES + 255) / 256, 256>>>();
    count_kernel<<<(E + 255) / 256, 256>>>(ei, E);
    scan_kernel<<<1, 1024>>>();
    fill_kernel<<<(E + 255) / 256, 256>>>(ei, E);

    // ---- encoder ----
    split_f(nodes, nhi, nlo, N_NODES * FEAT);
    tsplit_f(W1, wthi, wtlo, FEAT, HID);                     // [HID, FEAT]
    gemm3(nhi, nlo, wthi, wtlo, xw, N_NODES, HID, FEAT, 2);
    gcn_agg_kernel<<<N_NODES, HID>>>(xw, b1, x1, HID, 1);

    split_f(x1, xhi, xlo, N_NODES * HID);
    tsplit_f(W2, wthi, wtlo, HID, HID);
    gemm3(xhi, xlo, wthi, wtlo, xw, N_NODES, HID, HID, 4);
    gcn_agg_kernel<<<N_NODES, HID>>>(xw, b2, x2, HID, 1);

    // ---- assignment: s = (A_dn @ x2) @ Wp + bp ; softmax (emits s fp32 + bf16 hi/lo) ----
    y_agg_kernel<<<N_NODES, HID>>>(x2, x1);                  // y (reuse x1) = A_dn x2
    split_f(x1, xhi, xlo, N_NODES * HID);
    tsplit_f(Wp, wthi, wtlo, HID, KCL);                      // [KCL, HID]
    gemm3(xhi, xlo, wthi, wtlo, s, N_NODES, KCL, HID, 1);    // s = y Wp
    softmax_ent_kernel<<<N_NODES, 256>>>(s, bp, shi, slo);

    // ---- pooling ----
    tsplit_f(s, sthi, stlo, N_NODES, KCL);                   // S^T [KCL, N]
    tsplit_f(x2, xhi, xlo, N_NODES, HID);                    // x2^T [HID, N]
    gemm3(sthi, stlo, xhi, xlo, xp, KCL, HID, N_NODES, 16);  // xp = S^T x2 (signed)
    t_agg_kernel<<<N_NODES, 256>>>(shi, t);                  // t = A S  (positive, bf16 gather)
    tsplit_f(t, tthi, ttlo, N_NODES, KCL);                   // t^T [KCL, N]
    gemm1(sthi, tthi, adjp, KCL, KCL, N_NODES, 4);           // adjp = S^T A S (positive)
    gemm1(sthi, sthi, G, KCL, KCL, N_NODES, 4);              // G = S^T S (positive)

    // link-loss pieces: cross = <A S, S> = <t, s>
    dot_kernel<<<1024, 256>>>(t, s, N_NODES * KCL, 1);
    dupsq_kernel<<<N_NODES, 256>>>();
    sq_reduce_kernel<<<1024, 256>>>(G, KCL * KCL, 3);

    // ---- un-pool ----
    tsplit_f(xp, xpthi, xptlo, KCL, HID);                    // xp^T [HID, KCL]
    gemm3(shi, slo, xpthi, xptlo, xo, N_NODES, HID, KCL, 4); // xo = S xp (signed)
    tsplit_f(adjp, apthi, aptlo, KCL, KCL);                  // adjp^T
    gemm1_bf16(shi, apthi, mbhi, N_NODES, KCL, KCL);         // Mb = S adjp (positive, bf16 out)
    gemm1(mbhi, shi, out_adj, N_NODES, N_NODES, KCL, 1);     // adj_out = Mb S^T (positive)

    // ---- decoder ----
    split_f(xo, xhi, xlo, N_NODES * HID);
    tsplit_f(W3, wthi, wtlo, HID, HID);
    gemm3(xhi, xlo, wthi, wtlo, xw, N_NODES, HID, HID, 4);
    gcn_agg_kernel<<<N_NODES, HID>>>(xw, b3, x1, HID, 1);

    split_f(x1, xhi, xlo, N_NODES * HID);
    tsplit_f(W4, wthi, wtlo, HID, HID);
    gemm3(xhi, xlo, wthi, wtlo, xw, N_NODES, HID, HID, 4);
    gcn_agg_kernel<<<N_NODES, HID>>>(xw, b4, x2, HID, 1);

    split_f(x2, xhi, xlo, N_NODES * HID);
    tsplit_f(W5, wthi, wtlo, HID, FEAT);                     // [FEAT, HID]
    gemm3(xhi, xlo, wthi, wtlo, xw, N_NODES, FEAT, HID, 4);
    gcn_agg_kernel<<<N_NODES, FEAT>>>(xw, b5, out_x, FEAT, 0);

    // scalars
    finalize_kernel<<<1, 1>>>(out_link, out_ent);
}

// round 13
// speedup vs baseline: 1.6557x; 1.0268x over previous
#include <cuda_runtime.h>
#include <cuda_bf16.h>
#include <math.h>
#include <stdint.h>

// Problem constants (fixed for this dataset)
#define N_NODES 4096
#define FEAT    128
#define HID     256
#define KCL     1024
#define NE      131072

// ==================== device scratch ====================
__device__ __align__(16) int   d_cnt_in [N_NODES];
__device__ __align__(16) int   d_cnt_out[N_NODES];
__device__ __align__(16) int   d_selfc  [N_NODES];
__device__ __align__(16) int   d_cur_in [N_NODES];
__device__ __align__(16) int   d_cur_out[N_NODES];
__device__ __align__(16) int   d_off_in [N_NODES];
__device__ __align__(16) int   d_off_out[N_NODES];
__device__ __align__(16) int   d_csc_src[NE];
__device__ __align__(16) int   d_csr_dst[NE];
__device__ __align__(16) float d_dis_sp [N_NODES];
__device__ __align__(16) float d_dis_dn [N_NODES];
__device__ double d_scal[4];   // [0]=ent [1]=cross [2]=sum adj^2 [3]=||G||^2

__device__ __align__(16) float g_x2 [N_NODES*HID];
__device__ __align__(16) float g_xw [N_NODES*KCL];
__device__ __align__(16) float g_s  [N_NODES*KCL];
__device__ __align__(16) float g_t  [N_NODES*KCL];
__device__ __align__(16) float g_xp [KCL*HID];
__device__ __align__(16) float g_adjp[KCL*KCL];
__device__ __align__(16) float g_G  [KCL*KCL];
__device__ __align__(16) float g_xo [N_NODES*HID];

// bf16 split operand buffers
__device__ __align__(16) __nv_bfloat16 g_nhi [N_NODES*FEAT],  g_nlo [N_NODES*FEAT];
__device__ __align__(16) __nv_bfloat16 g_xhi [N_NODES*HID],   g_xlo [N_NODES*HID];
__device__ __align__(16) __nv_bfloat16 g_wthi[KCL*HID],       g_wtlo[KCL*HID];
__device__ __align__(16) __nv_bfloat16 g_shi [N_NODES*KCL],   g_slo [N_NODES*KCL];
__device__ __align__(16) __nv_bfloat16 g_sthi[KCL*N_NODES],   g_stlo[KCL*N_NODES];
__device__ __align__(16) __nv_bfloat16 g_tthi[KCL*N_NODES],   g_ttlo[KCL*N_NODES];
__device__ __align__(16) __nv_bfloat16 g_xpthi[HID*KCL],      g_xptlo[HID*KCL];
__device__ __align__(16) __nv_bfloat16 g_apthi[KCL*KCL],      g_aptlo[KCL*KCL];
__device__ __align__(16) __nv_bfloat16 g_mbhi[N_NODES*KCL];

// ==================== setup kernels ====================
__global__ void init_zero_kernel() {
    int i = blockIdx.x * blockDim.x + threadIdx.x;
    if (i < N_NODES) {
        d_cnt_in[i] = 0; d_cnt_out[i] = 0; d_selfc[i] = 0;
        d_cur_in[i] = 0; d_cur_out[i] = 0;
    }
    if (i < 4) d_scal[i] = 0.0;
}

__global__ void zero_kernel(float* __restrict__ p, int n) {
    int i = (blockIdx.x * blockDim.x + threadIdx.x) * 4;
    if (i < n) *reinterpret_cast<float4*>(p + i) = make_float4(0.f, 0.f, 0.f, 0.f);
}

__global__ void count_kernel(const int* __restrict__ ei, int E) {
    int e = blockIdx.x * blockDim.x + threadIdx.x;
    if (e >= E) return;
    int r = ei[e];
    int c = ei[E + e];
    atomicAdd(&d_cnt_out[r], 1);
    atomicAdd(&d_cnt_in[c], 1);
    if (r == c) atomicAdd(&d_selfc[r], 1);
}

__global__ void scan_kernel() {
    __shared__ int sh[1024];
    int t = threadIdx.x;
    {
        int v = t * 4;
        int a0 = d_cnt_in[v], a1 = d_cnt_in[v+1], a2 = d_cnt_in[v+2], a3 = d_cnt_in[v+3];
        int tot = a0 + a1 + a2 + a3;
        sh[t] = tot; __syncthreads();
        for (int o = 1; o < 1024; o <<= 1) {
            int x = (t >= o) ? sh[t - o] : 0;
            __syncthreads();
            sh[t] += x;
            __syncthreads();
        }
        int excl = sh[t] - tot;
        d_off_in[v]   = excl;
        d_off_in[v+1] = excl + a0;
        d_off_in[v+2] = excl + a0 + a1;
        d_off_in[v+3] = excl + a0 + a1 + a2;
        d_dis_sp[v]   = rsqrtf((float)(a0 + 1));
        d_dis_sp[v+1] = rsqrtf((float)(a1 + 1));
        d_dis_sp[v+2] = rsqrtf((float)(a2 + 1));
        d_dis_sp[v+3] = rsqrtf((float)(a3 + 1));
        __syncthreads();
    }
    {
        int v = t * 4;
        int a0 = d_cnt_out[v], a1 = d_cnt_out[v+1], a2 = d_cnt_out[v+2], a3 = d_cnt_out[v+3];
        int tot = a0 + a1 + a2 + a3;
        sh[t] = tot; __syncthreads();
        for (int o = 1; o < 1024; o <<= 1) {
            int x = (t >= o) ? sh[t - o] : 0;
            __syncthreads();
            sh[t] += x;
            __syncthreads();
        }
        int excl = sh[t] - tot;
        d_off_out[v]   = excl;
        d_off_out[v+1] = excl + a0;
        d_off_out[v+2] = excl + a0 + a1;
        d_off_out[v+3] = excl + a0 + a1 + a2;
        d_dis_dn[v]   = rsqrtf((float)(a0 - d_selfc[v]   + 1));
        d_dis_dn[v+1] = rsqrtf((float)(a1 - d_selfc[v+1] + 1));
        d_dis_dn[v+2] = rsqrtf((float)(a2 - d_selfc[v+2] + 1));
        d_dis_dn[v+3] = rsqrtf((float)(a3 - d_selfc[v+3] + 1));
    }
}

__global__ void fill_kernel(const int* __restrict__ ei, int E) {
    int e = blockIdx.x * blockDim.x + threadIdx.x;
    if (e >= E) return;
    int r = ei[e];
    int c = ei[E + e];
    int p = atomicAdd(&d_cur_in[c], 1);
    d_csc_src[d_off_in[c] + p] = r;
    int q = atomicAdd(&d_cur_out[r], 1);
    d_csr_dst[d_off_out[r] + q] = c;
}

// ==================== split / transpose-split ====================
__global__ void split_kernel(const float* __restrict__ in,
                             __nv_bfloat16* __restrict__ hi,
                             __nv_bfloat16* __restrict__ lo, int n)
{
    int i = (blockIdx.x * blockDim.x + threadIdx.x) * 4;
    if (i >= n) return;
    float4 v = *reinterpret_cast<const float4*>(in + i);
    __nv_bfloat16 h0 = __float2bfloat16(v.x);
    __nv_bfloat16 h1 = __float2bfloat16(v.y);
    __nv_bfloat16 h2 = __float2bfloat16(v.z);
    __nv_bfloat16 h3 = __float2bfloat16(v.w);
    __nv_bfloat162 hh0 = {h0, h1}, hh1 = {h2, h3};
    *reinterpret_cast<__nv_bfloat162*>(hi + i)     = hh0;
    *reinterpret_cast<__nv_bfloat162*>(hi + i + 2) = hh1;
    __nv_bfloat162 ll0 = {__float2bfloat16(v.x - __bfloat162float(h0)),
                          __float2bfloat16(v.y - __bfloat162float(h1))};
    __nv_bfloat162 ll1 = {__float2bfloat16(v.z - __bfloat162float(h2)),
                          __float2bfloat16(v.w - __bfloat162float(h3))};
    *reinterpret_cast<__nv_bfloat162*>(lo + i)     = ll0;
    *reinterpret_cast<__nv_bfloat162*>(lo + i + 2) = ll1;
}

// in fp32 [R,C] -> hi/lo bf16 [C,R]
__global__ void tsplit_kernel(const float* __restrict__ in,
                              __nv_bfloat16* __restrict__ hi,
                              __nv_bfloat16* __restrict__ lo, int R, int C)
{
    __shared__ float tile[32][33];
    int c0 = blockIdx.x * 32, r0 = blockIdx.y * 32;
    int tx = threadIdx.x, ty = threadIdx.y;  // 32 x 8
#pragma unroll
    for (int j = 0; j < 32; j += 8)
        tile[ty + j][tx] = in[(size_t)(r0 + ty + j) * C + c0 + tx];
    __syncthreads();
#pragma unroll
    for (int j = 0; j < 32; j += 8) {
        float x = tile[tx][ty + j];
        __nv_bfloat16 h = __float2bfloat16(x);
        size_t o = (size_t)(c0 + ty + j) * R + r0 + tx;
        hi[o] = h;
        lo[o] = __float2bfloat16(x - __bfloat162float(h));
    }
}

// ==================== HMMA common helpers ====================
__device__ __forceinline__ uint32_t smem_u32(const void* p) {
    uint32_t a;
    asm("{ .reg .u64 t; cvta.to.shared.u64 t, %1; cvt.u32.u64 %0, t; }" : "=r"(a) : "l"(p));
    return a;
}
__device__ __forceinline__ void cp_async16(uint32_t saddr, const void* gaddr) {
    asm volatile("cp.async.cg.shared.global [%0], [%1], 16;" :: "r"(saddr), "l"(gaddr));
}
__device__ __forceinline__ void cp_commit() {
    asm volatile("cp.async.commit_group;");
}
__device__ __forceinline__ void ldsm_x4(uint32_t* r, uint32_t addr) {
    asm volatile("ldmatrix.sync.aligned.m8n8.x4.shared.b16 {%0,%1,%2,%3}, [%4];"
        : "=r"(r[0]), "=r"(r[1]), "=r"(r[2]), "=r"(r[3]) : "r"(addr));
}
__device__ __forceinline__ void mma_bf16(float* d, const uint32_t* a, uint32_t b0, uint32_t b1) {
    asm volatile(
        "mma.sync.aligned.m16n8k16.row.col.f32.bf16.bf16.f32 "
        "{%0,%1,%2,%3}, {%4,%5,%6,%7}, {%8,%9}, {%0,%1,%2,%3};"
        : "+f"(d[0]), "+f"(d[1]), "+f"(d[2]), "+f"(d[3])
        : "r"(a[0]), "r"(a[1]), "r"(a[2]), "r"(a[3]), "r"(b0), "r"(b1));
}
__device__ __forceinline__ uint32_t sw128(uint32_t off) {
    return off ^ ((off >> 3) & 0x70);
}

// ==================== 3-term fused split GEMM ====================
// C[M,N] fp32 row-major (+)= Ahi*Bhi^T + Alo*Bhi^T + Ahi*Blo^T (K-major bf16).
// M,N mult of 128; per-z K slice mult of 64.  SMEM: 2 bufs x [Ahi|Alo|Bhi|Blo] x 16KB.
#define GEMM3_SMEM_BYTES 131072

__global__ __launch_bounds__(256) void gemm3_mma_kernel(
    const __nv_bfloat16* __restrict__ Ahi, const __nv_bfloat16* __restrict__ Alo,
    const __nv_bfloat16* __restrict__ Bhi, const __nv_bfloat16* __restrict__ Blo,
    float* __restrict__ C, int M, int N, int K)
{
    extern __shared__ char smem[];
    const uint32_t sbase = smem_u32(smem);
    const int tid = threadIdx.x, lane = tid & 31, wid = tid >> 5;
    const int bm = blockIdx.y * 128, bn = blockIdx.x * 128;
    const int wm = (wid >> 1) * 32;
    const int wn = (wid & 1) * 64;

    const int ksz = K / gridDim.z;
    const int k0  = blockIdx.z * ksz;
    const int nch = ksz >> 6;

    float acc[2][8][4];
#pragma unroll
    for (int mi = 0; mi < 2; mi++)
#pragma unroll
        for (int ni = 0; ni < 8; ni++)
#pragma unroll
            for (int q = 0; q < 4; q++) acc[mi][ni][q] = 0.f;

    int lrow[4], lcb[4];
    uint32_t lsw[4];
#pragma unroll
    for (int it = 0; it < 4; it++) {
        int u = tid + it * 256;
        lrow[it] = u >> 3;
        lcb[it]  = u & 7;
        lsw[it]  = sw128((uint32_t)(lrow[it] * 128 + lcb[it] * 16));
    }

    const int a_row = wm + (lane & 15);
    const int a_kof = (lane >> 4) * 8;
    const int b_row = wn + ((lane >> 4) << 3) + (lane & 7);
    const int b_kof = ((lane >> 3) & 1) * 8;

    auto issue = [&](int kc, int buf) {
        uint32_t sbuf = sbase + buf * 65536;
        const __nv_bfloat16* tp[4] = { Ahi, Alo, Bhi, Blo };
#pragma unroll
        for (int tI = 0; tI < 4; tI++) {
            int ro = (tI < 2) ? bm : bn;
            const __nv_bfloat16* P = tp[tI];
            uint32_t sdst = sbuf + tI * 16384;
#pragma unroll
            for (int it = 0; it < 4; it++)
                cp_async16(sdst + lsw[it],
                           P + (size_t)(ro + lrow[it]) * K + k0 + kc * 64 + lcb[it] * 8);
        }
        cp_commit();
    };

    issue(0, 0);
    for (int g = 0; g < nch; g++) {
        if (g + 1 < nch) {
            issue(g + 1, (g + 1) & 1);
            asm volatile("cp.async.wait_group 1;" ::: "memory");
        } else {
            asm volatile("cp.async.wait_group 0;" ::: "memory");
        }
        __syncthreads();
        uint32_t sbuf = sbase + (g & 1) * 65536;
        const uint32_t sAh = sbuf, sAl = sbuf + 16384, sBh = sbuf + 32768, sBl = sbuf + 49152;
#pragma unroll
        for (int kk = 0; kk < 64; kk += 16) {
            uint32_t ah[2][4], al[2][4], bh[4][4], bl[4][4];
#pragma unroll
            for (int mi = 0; mi < 2; mi++) {
                uint32_t off = sw128((uint32_t)((a_row + mi * 16) * 128 + (kk + a_kof) * 2));
                ldsm_x4(ah[mi], sAh + off);
                ldsm_x4(al[mi], sAl + off);
            }
#pragma unroll
            for (int np = 0; np < 4; np++) {
                uint32_t off = sw128((uint32_t)((b_row + np * 16) * 128 + (kk + b_kof) * 2));
                ldsm_x4(bh[np], sBh + off);
                ldsm_x4(bl[np], sBl + off);
            }
#pragma unroll
            for (int mi = 0; mi < 2; mi++)
#pragma unroll
                for (int ni = 0; ni < 8; ni++) {
                    uint32_t b0h = bh[ni >> 1][(ni & 1) * 2], b1h = bh[ni >> 1][(ni & 1) * 2 + 1];
                    uint32_t b0l = bl[ni >> 1][(ni & 1) * 2], b1l = bl[ni >> 1][(ni & 1) * 2 + 1];
                    mma_bf16(acc[mi][ni], ah[mi], b0h, b1h);
                    mma_bf16(acc[mi][ni], al[mi], b0h, b1h);
                    mma_bf16(acc[mi][ni], ah[mi], b0l, b1l);
                }
        }
        __syncthreads();
    }

    const int er = lane >> 2, ec = (lane & 3) * 2;
    if (gridDim.z == 1) {
#pragma unroll
        for (int mi = 0; mi < 2; mi++) {
            int row0 = bm + wm + mi * 16 + er;
#pragma unroll
            for (int ni = 0; ni < 8; ni++) {
                int col = bn + wn + ni * 8 + ec;
                *reinterpret_cast<float2*>(C + (size_t)row0 * N + col) =
                    make_float2(acc[mi][ni][0], acc[mi][ni][1]);
                *reinterpret_cast<float2*>(C + (size_t)(row0 + 8) * N + col) =
                    make_float2(acc[mi][ni][2], acc[mi][ni][3]);
            }
        }
    } else {
#pragma unroll
        for (int mi = 0; mi < 2; mi++) {
            int row0 = bm + wm + mi * 16 + er;
#pragma unroll
            for (int ni = 0; ni < 8; ni++) {
                int col = bn + wn + ni * 8 + ec;
                atomicAdd(C + (size_t)row0 * N + col,       acc[mi][ni][0]);
                atomicAdd(C + (size_t)row0 * N + col + 1,   acc[mi][ni][1]);
                atomicAdd(C + (size_t)(row0 + 8) * N + col,     acc[mi][ni][2]);
                atomicAdd(C + (size_t)(row0 + 8) * N + col + 1, acc[mi][ni][3]);
            }
        }
    }
}

// ==================== 1-term plain bf16 GEMM (positive chains) ====================
// OUT_BF16=0: C fp32 (split-K via atomics allowed). OUT_BF16=1: C bf16, SK must be 1.
#define GEMM1_SMEM_BYTES 65536

template <int OUT_BF16>
__global__ __launch_bounds__(256) void gemm1_mma_kernel(
    const __nv_bfloat16* __restrict__ A, const __nv_bfloat16* __restrict__ B,
    void* __restrict__ Cv, int M, int N, int K)
{
    extern __shared__ char smem[];
    const uint32_t sbase = smem_u32(smem);
    const int tid = threadIdx.x, lane = tid & 31, wid = tid >> 5;
    const int bm = blockIdx.y * 128, bn = blockIdx.x * 128;
    const int wm = (wid >> 1) * 32;
    const int wn = (wid & 1) * 64;

    const int ksz = K / gridDim.z;
    const int k0  = blockIdx.z * ksz;
    const int nch = ksz >> 6;

    float acc[2][8][4];
#pragma unroll
    for (int mi = 0; mi < 2; mi++)
#pragma unroll
        for (int ni = 0; ni < 8; ni++)
#pragma unroll
            for (int q = 0; q < 4; q++) acc[mi][ni][q] = 0.f;

    int lrow[4], lcb[4];
    uint32_t lsw[4];
#pragma unroll
    for (int it = 0; it < 4; it++) {
        int u = tid + it * 256;
        lrow[it] = u >> 3;
        lcb[it]  = u & 7;
        lsw[it]  = sw128((uint32_t)(lrow[it] * 128 + lcb[it] * 16));
    }

    const int a_row = wm + (lane & 15);
    const int a_kof = (lane >> 4) * 8;
    const int b_row = wn + ((lane >> 4) << 3) + (lane & 7);
    const int b_kof = ((lane >> 3) & 1) * 8;

    auto issue = [&](int kc, int buf) {
        uint32_t sbuf = sbase + buf * 32768;
#pragma unroll
        for (int it = 0; it < 4; it++) {
            int col = k0 + kc * 64 + lcb[it] * 8;
            cp_async16(sbuf + lsw[it],         A + (size_t)(bm + lrow[it]) * K + col);
            cp_async16(sbuf + 16384 + lsw[it], B + (size_t)(bn + lrow[it]) * K + col);
        }
        cp_commit();
    };

    issue(0, 0);
    for (int g = 0; g < nch; g++) {
        if (g + 1 < nch) {
            issue(g + 1, (g + 1) & 1);
            asm volatile("cp.async.wait_group 1;" ::: "memory");
        } else {
            asm volatile("cp.async.wait_group 0;" ::: "memory");
        }
        __syncthreads();
        uint32_t sbuf = sbase + (g & 1) * 32768;
        const uint32_t sA = sbuf, sB = sbuf + 16384;
#pragma unroll
        for (int kk = 0; kk < 64; kk += 16) {
            uint32_t af[2][4], bf[4][4];
#pragma unroll
            for (int mi = 0; mi < 2; mi++)
                ldsm_x4(af[mi], sA + sw128((uint32_t)((a_row + mi * 16) * 128 + (kk + a_kof) * 2)));
#pragma unroll
            for (int np = 0; np < 4; np++)
                ldsm_x4(bf[np], sB + sw128((uint32_t)((b_row + np * 16) * 128 + (kk + b_kof) * 2)));
#pragma unroll
            for (int mi = 0; mi < 2; mi++)
#pragma unroll
                for (int ni = 0; ni < 8; ni++)
                    mma_bf16(acc[mi][ni], af[mi],
                             bf[ni >> 1][(ni & 1) * 2], bf[ni >> 1][(ni & 1) * 2 + 1]);
        }
        __syncthreads();
    }

    const int er = lane >> 2, ec = (lane & 3) * 2;
    if (OUT_BF16) {
        __nv_bfloat16* C = (__nv_bfloat16*)Cv;
#pragma unroll
        for (int mi = 0; mi < 2; mi++) {
            int row0 = bm + wm + mi * 16 + er;
#pragma unroll
            for (int ni = 0; ni < 8; ni++) {
                int col = bn + wn + ni * 8 + ec;
                __nv_bfloat162 p0 = {__float2bfloat16(acc[mi][ni][0]),
                                     __float2bfloat16(acc[mi][ni][1])};
                __nv_bfloat162 p1 = {__float2bfloat16(acc[mi][ni][2]),
                                     __float2bfloat16(acc[mi][ni][3])};
                *reinterpret_cast<__nv_bfloat162*>(C + (size_t)row0 * N + col)       = p0;
                *reinterpret_cast<__nv_bfloat162*>(C + (size_t)(row0 + 8) * N + col) = p1;
            }
        }
    } else {
        float* C = (float*)Cv;
        if (gridDim.z == 1) {
#pragma unroll
            for (int mi = 0; mi < 2; mi++) {
                int row0 = bm + wm + mi * 16 + er;
#pragma unroll
                for (int ni = 0; ni < 8; ni++) {
                    int col = bn + wn + ni * 8 + ec;
                    *reinterpret_cast<float2*>(C + (size_t)row0 * N + col) =
                        make_float2(acc[mi][ni][0], acc[mi][ni][1]);
                    *reinterpret_cast<float2*>(C + (size_t)(row0 + 8) * N + col) =
                        make_float2(acc[mi][ni][2], acc[mi][ni][3]);
                }
            }
        } else {
#pragma unroll
            for (int mi = 0; mi < 2; mi++) {
                int row0 = bm + wm + mi * 16 + er;
#pragma unroll
                for (int ni = 0; ni < 8; ni++) {
                    int col = bn + wn + ni * 8 + ec;
                    atomicAdd(C + (size_t)row0 * N + col,       acc[mi][ni][0]);
                    atomicAdd(C + (size_t)row0 * N + col + 1,   acc[mi][ni][1]);
                    atomicAdd(C + (size_t)(row0 + 8) * N + col,     acc[mi][ni][2]);
                    atomicAdd(C + (size_t)(row0 + 8) * N + col + 1, acc[mi][ni][3]);
                }
            }
        }
    }
}

// ==================== sparse aggregation ====================
// fp32-output variant (x2 and final out_x)
__global__ void gcn_agg_kernel(const float* __restrict__ xw, const float* __restrict__ bias,
                               float* __restrict__ out, int F, int do_tanh)
{
    int v = blockIdx.x, f = threadIdx.x;
    __shared__ int   sid[256];
    __shared__ float snw[256];
    int nb = d_cnt_in[v], base = d_off_in[v];
    float dv = d_dis_sp[v];
    float acc = 0.f;
    int CH = blockDim.x;
    for (int c0 = 0; c0 < nb; c0 += CH) {
        int m = min(CH, nb - c0);
        __syncthreads();
        if (f < m) {
            int r = d_csc_src[base + c0 + f];
            sid[f] = r;
            snw[f] = d_dis_sp[r];
        }
        __syncthreads();
#pragma unroll 4
        for (int e = 0; e < m; e++)
            acc += snw[e] * xw[(size_t)sid[e] * F + f];
    }
    float o = dv * acc + dv * dv * xw[(size_t)v * F + f] + bias[f];
    out[(size_t)v * F + f] = do_tanh ? tanhf(o) : o;
}

// bf16 hi/lo-output variant (tanh layers consumed only by a GEMM)
__global__ void gcn_agg_split_kernel(const float* __restrict__ xw, const float* __restrict__ bias,
                                     __nv_bfloat16* __restrict__ hi,
                                     __nv_bfloat16* __restrict__ lo, int F)
{
    int v = blockIdx.x, f = threadIdx.x;
    __shared__ int   sid[256];
    __shared__ float snw[256];
    int nb = d_cnt_in[v], base = d_off_in[v];
    float dv = d_dis_sp[v];
    float acc = 0.f;
    int CH = blockDim.x;
    for (int c0 = 0; c0 < nb; c0 += CH) {
        int m = min(CH, nb - c0);
        __syncthreads();
        if (f < m) {
            int r = d_csc_src[base + c0 + f];
            sid[f] = r;
            snw[f] = d_dis_sp[r];
        }
        __syncthreads();
#pragma unroll 4
        for (int e = 0; e < m; e++)
            acc += snw[e] * xw[(size_t)sid[e] * F + f];
    }
    float o = tanhf(dv * acc + dv * dv * xw[(size_t)v * F + f] + bias[f]);
    __nv_bfloat16 h = __float2bfloat16(o);
    hi[(size_t)v * F + f] = h;
    lo[(size_t)v * F + f] = __float2bfloat16(o - __bfloat162float(h));
}

// y = A_dn x2 emitted directly as bf16 hi/lo (consumer: gemm3 only)
__global__ void y_agg_split_kernel(const float* __restrict__ x2,
                                   __nv_bfloat16* __restrict__ hi,
                                   __nv_bfloat16* __restrict__ lo)
{
    int v = blockIdx.x, f = threadIdx.x;  // 256 threads, 1 col each
    __shared__ int   sid[256];
    __shared__ float snw[256];
    int nb = d_cnt_out[v], base = d_off_out[v];
    float dv = d_dis_dn[v];
    float acc = 0.f;
    for (int c0 = 0; c0 < nb; c0 += 256) {
        int m = min(256, nb - c0);
        __syncthreads();
        if (f < m) {
            int c = d_csr_dst[base + c0 + f];
            sid[f] = c;
            snw[f] = (c == v) ? 0.f : d_dis_dn[c];
        }
        __syncthreads();
#pragma unroll 4
        for (int e = 0; e < m; e++)
            acc += snw[e] * x2[(size_t)sid[e] * HID + f];
    }
    float o = dv * acc + dv * dv * x2[(size_t)v * HID + f];
    __nv_bfloat16 h = __float2bfloat16(o);
    hi[(size_t)v * HID + f] = h;
    lo[(size_t)v * HID + f] = __float2bfloat16(o - __bfloat162float(h));
}

// t[v,:] = sum over CSR edges of bf16(s)[c,:]  (gathers bf16 hi version of s)
__global__ void t_agg_kernel(const __nv_bfloat16* __restrict__ sh, float* __restrict__ tt)
{
    int v = blockIdx.x, t = threadIdx.x;
    __shared__ int sid[256];
    int nb = d_cnt_out[v], base = d_off_out[v];
    float a0 = 0.f, a1 = 0.f, a2 = 0.f, a3 = 0.f;
    for (int c0 = 0; c0 < nb; c0 += 256) {
        int m = min(256, nb - c0);
        __syncthreads();
        if (t < m) sid[t] = d_csr_dst[base + c0 + t];
        __syncthreads();
#pragma unroll 4
        for (int e = 0; e < m; e++) {
            const __nv_bfloat16* xr = sh + (size_t)sid[e] * KCL;
            __nv_bfloat162 p0 = *reinterpret_cast<const __nv_bfloat162*>(xr + t * 2);
            a0 += __bfloat162float(p0.x);
            a1 += __bfloat162float(p0.y);
            __nv_bfloat162 p1 = *reinterpret_cast<const __nv_bfloat162*>(xr + 512 + t * 2);
            a2 += __bfloat162float(p1.x);
            a3 += __bfloat162float(p1.y);
        }
    }
    tt[(size_t)v * KCL + t * 2]       = a0;
    tt[(size_t)v * KCL + t * 2 + 1]   = a1;
    tt[(size_t)v * KCL + 512 + t * 2]     = a2;
    tt[(size_t)v * KCL + 512 + t * 2 + 1] = a3;
}

// in-place: s = softmax(s + bp); writes fp32 s, bf16 hi/lo; accumulates entropy
__global__ void softmax_ent_kernel(float* __restrict__ s, const float* __restrict__ bp,
                                   __nv_bfloat16* __restrict__ shi,
                                   __nv_bfloat16* __restrict__ slo)
{
    int v = blockIdx.x, t = threadIdx.x;
    float* row = s + (size_t)v * KCL;
    float x0 = row[t]       + bp[t];
    float x1 = row[t + 256] + bp[t + 256];
    float x2 = row[t + 512] + bp[t + 512];
    float x3 = row[t + 768] + bp[t + 768];
    __shared__ float red[256];
    float mx = fmaxf(fmaxf(x0, x1), fmaxf(x2, x3));
    red[t] = mx; __syncthreads();
    for (int o = 128; o > 0; o >>= 1) { if (t < o) red[t] = fmaxf(red[t], red[t + o]); __syncthreads(); }
    float m = red[0]; __syncthreads();
    float e0 = expf(x0 - m), e1 = expf(x1 - m), e2 = expf(x2 - m), e3 = expf(x3 - m);
    red[t] = e0 + e1 + e2 + e3; __syncthreads();
    for (int o = 128; o > 0; o >>= 1) { if (t < o) red[t] += red[t + o]; __syncthreads(); }
    float inv = 1.0f / red[0]; __syncthreads();
    float p0 = e0 * inv, p1 = e1 * inv, p2 = e2 * inv, p3 = e3 * inv;
    row[t] = p0; row[t + 256] = p1; row[t + 512] = p2; row[t + 768] = p3;
    __nv_bfloat16* hrow = shi + (size_t)v * KCL;
    __nv_bfloat16* lrow = slo + (size_t)v * KCL;
    float p[4] = {p0, p1, p2, p3};
#pragma unroll
    for (int q = 0; q < 4; q++) {
        __nv_bfloat16 h = __float2bfloat16(p[q]);
        hrow[t + q * 256] = h;
        lrow[t + q * 256] = __float2bfloat16(p[q] - __bfloat162float(h));
    }
    float ent = -(p0 * logf(p0 + 1e-15f) + p1 * logf(p1 + 1e-15f) +
                  p2 * logf(p2 + 1e-15f) + p3 * logf(p3 + 1e-15f));
    red[t] = ent; __syncthreads();
    for (int o = 128; o > 0; o >>= 1) { if (t < o) red[t] += red[t + o]; __syncthreads(); }
    if (t == 0) atomicAdd(&d_scal[0], (double)red[0]);
}

// dot product of two big arrays -> d_scal[slot]  (cross = <A S, S> = <t, s>)
__global__ void dot_kernel(const float* __restrict__ a, const float* __restrict__ b,
                           int n, int slot)
{
    int i = (blockIdx.x * blockDim.x + threadIdx.x) * 4;
    float p = 0.f;
    int stride = gridDim.x * blockDim.x * 4;
    for (; i < n; i += stride) {
        float4 va = *reinterpret_cast<const float4*>(a + i);
        float4 vb = *reinterpret_cast<const float4*>(b + i);
        p += va.x * vb.x + va.y * vb.y + va.z * vb.z + va.w * vb.w;
    }
    __shared__ float red[256];
    red[threadIdx.x] = p; __syncthreads();
    for (int o = 128; o > 0; o >>= 1) { if (threadIdx.x < o) red[threadIdx.x] += red[threadIdx.x + o]; __syncthreads(); }
    if (threadIdx.x == 0) atomicAdd(&d_scal[slot], (double)red[0]);
}

__global__ void dupsq_kernel()
{
    int v = blockIdx.x, t = threadIdx.x;
    int nb = d_cnt_out[v], base = d_off_out[v];
    int tot = 0;
    for (int i = t; i < nb; i += blockDim.x) {
        int ci = d_csr_dst[base + i];
        int c = 0;
        for (int j = 0; j < nb; j++) c += (d_csr_dst[base + j] == ci) ? 1 : 0;
        tot += c;
    }
    __shared__ int red[256];
    red[t] = tot; __syncthreads();
    for (int o = 128; o > 0; o >>= 1) { if (t < o) red[t] += red[t + o]; __syncthreads(); }
    if (t == 0 && red[0] != 0) atomicAdd(&d_scal[2], (double)red[0]);
}

__global__ void sq_reduce_kernel(const float* __restrict__ a, int n, int slot)
{
    int i = blockIdx.x * blockDim.x + threadIdx.x;
    float p = 0.f;
    for (; i < n; i += gridDim.x * blockDim.x) { float x = a[i]; p += x * x; }
    __shared__ float red[256];
    red[threadIdx.x] = p; __syncthreads();
    for (int o = 128; o > 0; o >>= 1) { if (threadIdx.x < o) red[threadIdx.x] += red[threadIdx.x + o]; __syncthreads(); }
    if (threadIdx.x == 0) atomicAdd(&d_scal[slot], (double)red[0]);
}

__global__ void finalize_kernel(float* __restrict__ out_link, float* __restrict__ out_ent)
{
    double v = d_scal[2] - 2.0 * d_scal[1] + d_scal[3];
    if (v < 0.0) v = 0.0;
    *out_link = (float)(0.1 * sqrt(v) / ((double)N_NODES * (double)N_NODES));
    *out_ent  = (float)(0.1 * (d_scal[0] / (double)N_NODES));
}

// ==================== host side ====================
static void gemm3(const __nv_bfloat16* Ah, const __nv_bfloat16* Al,
                  const __nv_bfloat16* Bh, const __nv_bfloat16* Bl,
                  float* C, int M, int N, int K, int SK)
{
    static int attr_done = 0;
    if (!attr_done) {
        cudaFuncSetAttribute(gemm3_mma_kernel, cudaFuncAttributeMaxDynamicSharedMemorySize,
                             GEMM3_SMEM_BYTES);
        attr_done = 1;
    }
    if (SK > 1)
        zero_kernel<<<((M * N) / 4 + 255) / 256, 256>>>(C, M * N);
    gemm3_mma_kernel<<<dim3(N / 128, M / 128, SK), 256, GEMM3_SMEM_BYTES>>>(Ah, Al, Bh, Bl, C, M, N, K);
}
static void gemm1(const __nv_bfloat16* A, const __nv_bfloat16* B,
                  float* C, int M, int N, int K, int SK)
{
    static int attr_done = 0;
    if (!attr_done) {
        cudaFuncSetAttribute(gemm1_mma_kernel<0>, cudaFuncAttributeMaxDynamicSharedMemorySize,
                             GEMM1_SMEM_BYTES);
        attr_done = 1;
    }
    if (SK > 1)
        zero_kernel<<<((M * N) / 4 + 255) / 256, 256>>>(C, M * N);
    gemm1_mma_kernel<0><<<dim3(N / 128, M / 128, SK), 256, GEMM1_SMEM_BYTES>>>(A, B, C, M, N, K);
}
static void gemm1_bf16(const __nv_bfloat16* A, const __nv_bfloat16* B,
                       __nv_bfloat16* C, int M, int N, int K)
{
    static int attr_done = 0;
    if (!attr_done) {
        cudaFuncSetAttribute(gemm1_mma_kernel<1>, cudaFuncAttributeMaxDynamicSharedMemorySize,
                             GEMM1_SMEM_BYTES);
        attr_done = 1;
    }
    gemm1_mma_kernel<1><<<dim3(N / 128, M / 128, 1), 256, GEMM1_SMEM_BYTES>>>(A, B, C, M, N, K);
}
static void split_f(const float* in, __nv_bfloat16* hi, __nv_bfloat16* lo, int n)
{
    split_kernel<<<(n / 4 + 255) / 256, 256>>>(in, hi, lo, n);
}
static void tsplit_f(const float* in, __nv_bfloat16* hi, __nv_bfloat16* lo, int R, int C)
{
    tsplit_kernel<<<dim3(C / 32, R / 32), dim3(32, 8)>>>(in, hi, lo, R, C);
}

extern "C" void kernel_launch(void* const* d_in, const int* in_sizes, int n_in,
                              void* d_out, int out_size)
{
    const float* nodes = (const float*)d_in[0];
    const int*   ei    = (const int*)d_in[1];
    const float* W1 = (const float*)d_in[3];  const float* b1 = (const float*)d_in[4];
    const float* W2 = (const float*)d_in[5];  const float* b2 = (const float*)d_in[6];
    const float* Wp = (const float*)d_in[7];  const float* bp = (const float*)d_in[8];
    const float* W3 = (const float*)d_in[9];  const float* b3 = (const float*)d_in[10];
    const float* W4 = (const float*)d_in[11]; const float* b4 = (const float*)d_in[12];
    const float* W5 = (const float*)d_in[13]; const float* b5 = (const float*)d_in[14];
    int E = in_sizes[1] / 2;

    float* out      = (float*)d_out;
    float* out_x    = out;
    float* out_adj  = out + (size_t)N_NODES * FEAT;
    float* out_link = out + (size_t)N_NODES * FEAT + (size_t)N_NODES * N_NODES;
    float* out_ent  = out_link + 1;

    float *x2, *xw, *s, *t, *xp, *adjp, *G, *xo;
    cudaGetSymbolAddress((void**)&x2,   g_x2);
    cudaGetSymbolAddress((void**)&xw,   g_xw);
    cudaGetSymbolAddress((void**)&s,    g_s);
    cudaGetSymbolAddress((void**)&t,    g_t);
    cudaGetSymbolAddress((void**)&xp,   g_xp);
    cudaGetSymbolAddress((void**)&adjp, g_adjp);
    cudaGetSymbolAddress((void**)&G,    g_G);
    cudaGetSymbolAddress((void**)&xo,   g_xo);

    __nv_bfloat16 *nhi,*nlo,*xhi,*xlo,*wthi,*wtlo,*shi,*slo,*sthi,*stlo;
    __nv_bfloat16 *tthi,*ttlo,*xpthi,*xptlo,*apthi,*aptlo,*mbhi;
    cudaGetSymbolAddress((void**)&nhi,  g_nhi);  cudaGetSymbolAddress((void**)&nlo,  g_nlo);
    cudaGetSymbolAddress((void**)&xhi,  g_xhi);  cudaGetSymbolAddress((void**)&xlo,  g_xlo);
    cudaGetSymbolAddress((void**)&wthi, g_wthi); cudaGetSymbolAddress((void**)&wtlo, g_wtlo);
    cudaGetSymbolAddress((void**)&shi,  g_shi);  cudaGetSymbolAddress((void**)&slo,  g_slo);
    cudaGetSymbolAddress((void**)&sthi, g_sthi); cudaGetSymbolAddress((void**)&stlo, g_stlo);
    cudaGetSymbolAddress((void**)&tthi, g_tthi); cudaGetSymbolAddress((void**)&ttlo, g_ttlo);
    cudaGetSymbolAddress((void**)&xpthi,g_xpthi);cudaGetSymbolAddress((void**)&xptlo,g_xptlo);
    cudaGetSymbolAddress((void**)&apthi,g_apthi);cudaGetSymbolAddress((void**)&aptlo,g_aptlo);
    cudaGetSymbolAddress((void**)&mbhi, g_mbhi);

    // graph preprocessing
    init_zero_kernel<<<(N_NODES + 255) / 256, 256>>>();
    count_kernel<<<(E + 255) / 256, 256>>>(ei, E);
    scan_kernel<<<1, 1024>>>();
    fill_kernel<<<(E + 255) / 256, 256>>>(ei, E);

    // ---- encoder ----
    split_f(nodes, nhi, nlo, N_NODES * FEAT);
    tsplit_f(W1, wthi, wtlo, FEAT, HID);                     // [HID, FEAT]
    gemm3(nhi, nlo, wthi, wtlo, xw, N_NODES, HID, FEAT, 2);
    gcn_agg_split_kernel<<<N_NODES, HID>>>(xw, b1, xhi, xlo, HID);   // x1 = tanh(.) -> bf16 direct

    tsplit_f(W2, wthi, wtlo, HID, HID);
    gemm3(xhi, xlo, wthi, wtlo, xw, N_NODES, HID, HID, 4);
    gcn_agg_kernel<<<N_NODES, HID>>>(xw, b2, x2, HID, 1);            // x2 fp32 (multi-consumer)

    // ---- assignment: s = (A_dn @ x2) @ Wp + bp ; softmax (emits s fp32 + bf16 hi/lo) ----
    y_agg_split_kernel<<<N_NODES, HID>>>(x2, xhi, xlo);              // y = A_dn x2 -> bf16 direct
    tsplit_f(Wp, wthi, wtlo, HID, KCL);                      // [KCL, HID]
    gemm3(xhi, xlo, wthi, wtlo, s, N_NODES, KCL, HID, 1);    // s = y Wp
    softmax_ent_kernel<<<N_NODES, 256>>>(s, bp, shi, slo);

    // ---- pooling ----
    tsplit_f(s, sthi, stlo, N_NODES, KCL);                   // S^T [KCL, N]
    tsplit_f(x2, xhi, xlo, N_NODES, HID);                    // x2^T [HID, N]
    gemm3(sthi, stlo, xhi, xlo, xp, KCL, HID, N_NODES, 16);  // xp = S^T x2 (signed)
    t_agg_kernel<<<N_NODES, 256>>>(shi, t);                  // t = A S  (positive, bf16 gather)
    tsplit_f(t, tthi, ttlo, N_NODES, KCL);                   // t^T [KCL, N]
    gemm1(sthi, tthi, adjp, KCL, KCL, N_NODES, 4);           // adjp = S^T A S (positive)
    gemm1(sthi, sthi, G, KCL, KCL, N_NODES, 4);              // G = S^T S (positive)

    // link-loss pieces: cross = <A S, S> = <t, s>
    dot_kernel<<<1024, 256>>>(t, s, N_NODES * KCL, 1);
    dupsq_kernel<<<N_NODES, 256>>>();
    sq_reduce_kernel<<<1024, 256>>>(G, KCL * KCL, 3);

    // ---- un-pool ----
    tsplit_f(xp, xpthi, xptlo, KCL, HID);                    // xp^T [HID, KCL]
    gemm3(shi, slo, xpthi, xptlo, xo, N_NODES, HID, KCL, 4); // xo = S xp (signed)
    tsplit_f(adjp, apthi, aptlo, KCL, KCL);                  // adjp^T
    gemm1_bf16(shi, apthi, mbhi, N_NODES, KCL, KCL);         // Mb = S adjp (positive, bf16 out)
    gemm1(mbhi, shi, out_adj, N_NODES, N_NODES, KCL, 1);     // adj_out = Mb S^T (positive)

    // ---- decoder ----
    split_f(xo, xhi, xlo, N_NODES * HID);
    tsplit_f(W3, wthi, wtlo, HID, HID);
    gemm3(xhi, xlo, wthi, wtlo, xw, N_NODES, HID, HID, 4);
    gcn_agg_split_kernel<<<N_NODES, HID>>>(xw, b3, xhi, xlo, HID);   // -> bf16 direct

    tsplit_f(W4, wthi, wtlo, HID, HID);
    gemm3(xhi, xlo, wthi, wtlo, xw, N_NODES, HID, HID, 4);
    gcn_agg_split_kernel<<<N_NODES, HID>>>(xw, b4, xhi, xlo, HID);   // -> bf16 direct

    tsplit_f(W5, wthi, wtlo, HID, FEAT);                     // [FEAT, HID]
    gemm3(xhi, xlo, wthi, wtlo, xw, N_NODES, FEAT, HID, 4);
    gcn_agg_kernel<<<N_NODES, FEAT>>>(xw, b5, out_x, FEAT, 0);

    // scalars
    finalize_kernel<<<1, 1>>>(out_link, out_ent);
}